// round 1
// baseline (speedup 1.0000x reference)
#include <cuda_runtime.h>
#include <math.h>

#define SEQ 4096
#define DM  1024
#define NH  16
#define DK  64

// scratch (no allocs allowed)
__device__ float g_q [NH * SEQ * DK];
__device__ float g_k [NH * SEQ * DK];
__device__ float g_v [NH * SEQ * DK];
__device__ float g_ao[SEQ * DM];

// ---------------------------------------------------------------------------
// Tiled SGEMM, C[m,n] = sum_k A[m,k] * B[n,k]   (both operands K-contiguous)
// BM=BN=64, BK=16, 256 threads, 4x4 register tile per thread.
// MODE 0: plain [M,N] store          (final Wo projection)
// MODE 1: head layout [h][s][dk]     (V projection)
// MODE 2: RoPE + head layout         (Q, K projections)
// ---------------------------------------------------------------------------
template <int MODE>
__global__ void __launch_bounds__(256)
gemm_nt(const float* __restrict__ A, const float* __restrict__ B,
        float* __restrict__ C, int M, int N, int K)
{
    __shared__ float As[16][65];
    __shared__ float Bs[16][65];

    const int bm  = blockIdx.y * 64;
    const int bn  = blockIdx.x * 64;
    const int tid = threadIdx.x;
    const int ty  = tid >> 4;      // 0..15
    const int tx  = tid & 15;      // 0..15

    const int lr = tid >> 2;          // load row 0..63
    const int lc = (tid & 3) << 2;    // load col4 0,4,8,12

    float acc[4][4] = {};

    for (int k0 = 0; k0 < K; k0 += 16) {
        float4 av = *(const float4*)(A + (size_t)(bm + lr) * K + k0 + lc);
        float4 bv = *(const float4*)(B + (size_t)(bn + lr) * K + k0 + lc);
        As[lc + 0][lr] = av.x; As[lc + 1][lr] = av.y;
        As[lc + 2][lr] = av.z; As[lc + 3][lr] = av.w;
        Bs[lc + 0][lr] = bv.x; Bs[lc + 1][lr] = bv.y;
        Bs[lc + 2][lr] = bv.z; Bs[lc + 3][lr] = bv.w;
        __syncthreads();

#pragma unroll
        for (int kk = 0; kk < 16; ++kk) {
            float a[4], b[4];
#pragma unroll
            for (int i = 0; i < 4; ++i) a[i] = As[kk][ty * 4 + i];
#pragma unroll
            for (int j = 0; j < 4; ++j) b[j] = Bs[kk][tx * 4 + j];
#pragma unroll
            for (int i = 0; i < 4; ++i)
#pragma unroll
                for (int j = 0; j < 4; ++j)
                    acc[i][j] += a[i] * b[j];
        }
        __syncthreads();
    }

#pragma unroll
    for (int i = 0; i < 4; ++i) {
        const int m  = bm + ty * 4 + i;
        const int n0 = bn + tx * 4;
        if (MODE == 0) {
            float* o = C + (size_t)m * N + n0;
            o[0] = acc[i][0]; o[1] = acc[i][1];
            o[2] = acc[i][2]; o[3] = acc[i][3];
        } else if (MODE == 1) {
            const int h  = n0 >> 6;
            const int d0 = n0 & 63;
            float* o = C + ((size_t)h * SEQ + m) * DK + d0;
            o[0] = acc[i][0]; o[1] = acc[i][1];
            o[2] = acc[i][2]; o[3] = acc[i][3];
        } else {
            // RoPE (interleaved pairs) + head layout
            const int h  = n0 >> 6;
            const int d0 = n0 & 63;                 // even
            const float pos  = (float)m;
            const float inv0 = powf(10000.f, -(float)d0 / 64.f);
            const float inv1 = powf(10000.f, -(float)(d0 + 2) / 64.f);
            float s0, c0, s1, c1;
            sincosf(pos * inv0, &s0, &c0);
            sincosf(pos * inv1, &s1, &c1);
            const float x0 = acc[i][0], x1 = acc[i][1];
            const float x2 = acc[i][2], x3 = acc[i][3];
            float* o = C + ((size_t)h * SEQ + m) * DK + d0;
            o[0] = x0 * c0 - x1 * s0;
            o[1] = x1 * c0 + x0 * s0;
            o[2] = x2 * c1 - x3 * s1;
            o[3] = x3 * c1 + x2 * s1;
        }
    }
}

// ---------------------------------------------------------------------------
// fp32 flash attention, causal. One block = (head, 64-query tile).
// Br = Bc = 64, 256 threads (16x16), 4x4 fragments for both S=QK^T and PV.
// Online softmax state (m, l) per query row, replicated across the 16 lanes
// that own that row; reductions via __shfl_xor over 16-lane groups.
// ---------------------------------------------------------------------------
__global__ void __launch_bounds__(256)
flash_attn(const float* __restrict__ Q, const float* __restrict__ K,
           const float* __restrict__ V, float* __restrict__ O)
{
    extern __shared__ float sm[];
    float* Qs = sm;                 // 64 x 65
    float* Ks = sm + 64 * 65;
    float* Vs = sm + 2 * 64 * 65;
    float* Ps = sm + 3 * 64 * 65;

    const int h   = blockIdx.y;
    const int qb  = blockIdx.x;
    const int tid = threadIdx.x;
    const int ty  = tid >> 4;
    const int tx  = tid & 15;

    const float* qh = Q + ((size_t)h * SEQ + (size_t)qb * 64) * DK;
    const float* kh = K + (size_t)h * SEQ * DK;
    const float* vh = V + (size_t)h * SEQ * DK;

    for (int idx = tid; idx < 64 * 64; idx += 256) {
        int r = idx >> 6, c = idx & 63;
        Qs[r * 65 + c] = qh[r * 64 + c];
    }

    float oacc[4][4] = {};
    float mrow[4], lrow[4];
#pragma unroll
    for (int i = 0; i < 4; ++i) { mrow[i] = -1e30f; lrow[i] = 0.f; }

    for (int kb = 0; kb <= qb; ++kb) {
        __syncthreads();  // prior PV reads of Ks/Vs done; also fences Qs fill on iter 0
        for (int idx = tid; idx < 64 * 64; idx += 256) {
            int r = idx >> 6, c = idx & 63;
            Ks[r * 65 + c] = kh[((size_t)kb * 64 + r) * 64 + c];
            Vs[r * 65 + c] = vh[((size_t)kb * 64 + r) * 64 + c];
        }
        __syncthreads();

        // S = Q K^T (64x64x64), scaled
        float sacc[4][4] = {};
#pragma unroll 8
        for (int d = 0; d < 64; ++d) {
            float qf[4], kf[4];
#pragma unroll
            for (int i = 0; i < 4; ++i) qf[i] = Qs[(ty * 4 + i) * 65 + d];
#pragma unroll
            for (int j = 0; j < 4; ++j) kf[j] = Ks[(tx * 4 + j) * 65 + d];
#pragma unroll
            for (int i = 0; i < 4; ++i)
#pragma unroll
                for (int j = 0; j < 4; ++j)
                    sacc[i][j] += qf[i] * kf[j];
        }

        const bool diag = (kb == qb);
#pragma unroll
        for (int i = 0; i < 4; ++i)
#pragma unroll
            for (int j = 0; j < 4; ++j) {
                sacc[i][j] *= 0.125f;  // 1/sqrt(64)
                if (diag && (tx * 4 + j) > (ty * 4 + i)) sacc[i][j] = -1e30f;
            }

        // online softmax per row
#pragma unroll
        for (int i = 0; i < 4; ++i) {
            float mt = sacc[i][0];
#pragma unroll
            for (int j = 1; j < 4; ++j) mt = fmaxf(mt, sacc[i][j]);
#pragma unroll
            for (int off = 1; off < 16; off <<= 1)
                mt = fmaxf(mt, __shfl_xor_sync(0xffffffffu, mt, off));
            const float mnew = fmaxf(mrow[i], mt);
            const float corr = __expf(mrow[i] - mnew);
            mrow[i] = mnew;
            float p[4], rs = 0.f;
#pragma unroll
            for (int j = 0; j < 4; ++j) { p[j] = __expf(sacc[i][j] - mnew); rs += p[j]; }
#pragma unroll
            for (int off = 1; off < 16; off <<= 1)
                rs += __shfl_xor_sync(0xffffffffu, rs, off);
            lrow[i] = lrow[i] * corr + rs;
#pragma unroll
            for (int j = 0; j < 4; ++j) oacc[i][j] *= corr;
#pragma unroll
            for (int j = 0; j < 4; ++j) Ps[(ty * 4 + i) * 65 + tx * 4 + j] = p[j];
        }
        __syncthreads();

        // O += P V (64x64x64)
#pragma unroll 8
        for (int kk = 0; kk < 64; ++kk) {
            float pf[4], vf[4];
#pragma unroll
            for (int i = 0; i < 4; ++i) pf[i] = Ps[(ty * 4 + i) * 65 + kk];
#pragma unroll
            for (int j = 0; j < 4; ++j) vf[j] = Vs[kk * 65 + tx * 4 + j];
#pragma unroll
            for (int i = 0; i < 4; ++i)
#pragma unroll
                for (int j = 0; j < 4; ++j)
                    oacc[i][j] += pf[i] * vf[j];
        }
    }

    // normalize + store to [s, h*dk]
#pragma unroll
    for (int i = 0; i < 4; ++i) {
        const float inv = 1.f / lrow[i];
        const int m = qb * 64 + ty * 4 + i;
        float* o = O + (size_t)m * DM + h * DK + tx * 4;
#pragma unroll
        for (int j = 0; j < 4; ++j) o[j] = oacc[i][j] * inv;
    }
}

// ---------------------------------------------------------------------------
extern "C" void kernel_launch(void* const* d_in, const int* in_sizes, int n_in,
                              void* d_out, int out_size)
{
    const float* x  = (const float*)d_in[0];
    const float* Wq = (const float*)d_in[1];
    const float* Wk = (const float*)d_in[2];
    const float* Wv = (const float*)d_in[3];
    const float* Wo = (const float*)d_in[4];

    float *qp, *kp, *vp, *aop;
    cudaGetSymbolAddress((void**)&qp,  g_q);
    cudaGetSymbolAddress((void**)&kp,  g_k);
    cudaGetSymbolAddress((void**)&vp,  g_v);
    cudaGetSymbolAddress((void**)&aop, g_ao);

    dim3 gg(DM / 64, SEQ / 64);   // (16, 64)
    gemm_nt<2><<<gg, 256>>>(x, Wq, qp, SEQ, DM, DM);
    gemm_nt<2><<<gg, 256>>>(x, Wk, kp, SEQ, DM, DM);
    gemm_nt<1><<<gg, 256>>>(x, Wv, vp, SEQ, DM, DM);

    const size_t smem = 4 * 64 * 65 * sizeof(float);  // 66,560 B
    cudaFuncSetAttribute(flash_attn, cudaFuncAttributeMaxDynamicSharedMemorySize, (int)smem);
    flash_attn<<<dim3(SEQ / 64, NH), 256, smem>>>(qp, kp, vp, aop);

    gemm_nt<0><<<gg, 256>>>(aop, Wo, (float*)d_out, SEQ, DM, DM);
}

// round 2
// speedup vs baseline: 1.3831x; 1.3831x over previous
#include <cuda_runtime.h>
#include <math.h>

#define SEQ 4096
#define DM  1024
#define NH  16
#define DK  64

// scratch (no allocs allowed)
__device__ float g_q [NH * SEQ * DK];
__device__ float g_k [NH * SEQ * DK];
__device__ float g_v [NH * SEQ * DK];
__device__ float g_ao[SEQ * DM];

// ---------------------------------------------------------------------------
// Tiled SGEMM, C[m,n] = sum_k A[m,k] * B[n,k]  (both K-contiguous).
// BM=BN=128, BK=16, 256 threads, 8x8 register tile per thread.
// smem holds tiles k-major (As[k][m]) so a-frags are broadcasts and b-frags
// are contiguous float4 loads.
// MODE 0: plain [M,N] store          (final Wo projection)
// MODE 1: head layout [h][s][dk]     (V projection)
// MODE 2: RoPE + head layout         (Q, K projections)
// ---------------------------------------------------------------------------
template <int MODE>
__global__ void __launch_bounds__(256, 2)
gemm_nt(const float* __restrict__ A, const float* __restrict__ B,
        float* __restrict__ C, int M, int N, int K)
{
    __shared__ float As[16][132];
    __shared__ float Bs[16][132];

    const int bm  = blockIdx.y * 128;
    const int bn  = blockIdx.x * 128;
    const int tid = threadIdx.x;
    const int ty  = tid >> 4;      // 0..15
    const int tx  = tid & 15;      // 0..15

    float acc[8][8] = {};

    for (int k0 = 0; k0 < K; k0 += 16) {
#pragma unroll
        for (int it = 0; it < 2; ++it) {
            const int idx = tid + it * 256;
            const int r   = idx >> 2;          // 0..127
            const int kq  = (idx & 3) << 2;    // 0,4,8,12
            float4 av = *(const float4*)(A + (size_t)(bm + r) * K + k0 + kq);
            float4 bv = *(const float4*)(B + (size_t)(bn + r) * K + k0 + kq);
            As[kq + 0][r] = av.x; As[kq + 1][r] = av.y;
            As[kq + 2][r] = av.z; As[kq + 3][r] = av.w;
            Bs[kq + 0][r] = bv.x; Bs[kq + 1][r] = bv.y;
            Bs[kq + 2][r] = bv.z; Bs[kq + 3][r] = bv.w;
        }
        __syncthreads();

#pragma unroll
        for (int kk = 0; kk < 16; ++kk) {
            float a[8], b[8];
            *(float4*)&a[0] = *(const float4*)&As[kk][4 * ty];
            *(float4*)&a[4] = *(const float4*)&As[kk][64 + 4 * ty];
            *(float4*)&b[0] = *(const float4*)&Bs[kk][4 * tx];
            *(float4*)&b[4] = *(const float4*)&Bs[kk][64 + 4 * tx];
#pragma unroll
            for (int i = 0; i < 8; ++i)
#pragma unroll
                for (int j = 0; j < 8; ++j)
                    acc[i][j] += a[i] * b[j];
        }
        __syncthreads();
    }

    // epilogue: rows {4ty..4ty+3, 64+4ty..+3}, col quads at 4tx and 64+4tx
#pragma unroll
    for (int i = 0; i < 8; ++i) {
        const int m = bm + ((i < 4) ? (4 * ty + i) : (64 + 4 * ty + i - 4));
#pragma unroll
        for (int jh = 0; jh < 2; ++jh) {
            const int n0 = bn + jh * 64 + 4 * tx;
            const float v0 = acc[i][jh * 4 + 0];
            const float v1 = acc[i][jh * 4 + 1];
            const float v2 = acc[i][jh * 4 + 2];
            const float v3 = acc[i][jh * 4 + 3];
            if (MODE == 0) {
                float4* o = (float4*)(C + (size_t)m * N + n0);
                *o = make_float4(v0, v1, v2, v3);
            } else if (MODE == 1) {
                const int h  = n0 >> 6;
                const int d0 = n0 & 63;
                float4* o = (float4*)(C + ((size_t)h * SEQ + m) * DK + d0);
                *o = make_float4(v0, v1, v2, v3);
            } else {
                // RoPE (interleaved pairs) + head layout
                const int h  = n0 >> 6;
                const int d0 = n0 & 63;             // even
                const float pos  = (float)m;
                const float inv0 = powf(10000.f, -(float)d0 / 64.f);
                const float inv1 = powf(10000.f, -(float)(d0 + 2) / 64.f);
                float s0, c0, s1, c1;
                sincosf(pos * inv0, &s0, &c0);
                sincosf(pos * inv1, &s1, &c1);
                float4* o = (float4*)(C + ((size_t)h * SEQ + m) * DK + d0);
                *o = make_float4(v0 * c0 - v1 * s0,
                                 v1 * c0 + v0 * s0,
                                 v2 * c1 - v3 * s1,
                                 v3 * c1 + v2 * s1);
            }
        }
    }
}

// ---------------------------------------------------------------------------
// fp32 flash attention, causal. One block = (head, 128-query tile).
// Br = Bc = 128, 256 threads. S fragments 8x8 (q x token), O fragments 8x4
// (q x dk). K stored transposed in smem (Kt[d][token]) so S b-frags are
// contiguous float4 loads; Q/P reads are broadcasts; V/P-store contiguous.
// ---------------------------------------------------------------------------
__global__ void __launch_bounds__(256)
flash_attn(const float* __restrict__ Q, const float* __restrict__ K,
           const float* __restrict__ V, float* __restrict__ O)
{
    extern __shared__ float sm[];
    float* Qs = sm;                   // 128 x 68
    float* Kt = Qs + 128 * 68;        // 64  x 132  (d, token)
    float* Vs = Kt + 64 * 132;        // 128 x 68   (token, dk)
    float* Ps = Vs + 128 * 68;        // 128 x 132  (q, token)

    const int h   = blockIdx.y;
    const int qb  = gridDim.x - 1 - blockIdx.x;   // heavy tiles first
    const int tid = threadIdx.x;
    const int ty  = tid >> 4;
    const int tx  = tid & 15;

    const int rb0 = 4 * ty;        // rows rb0..rb0+3 and 64+rb0..64+rb0+3
    const int cb0 = 4 * tx;        // token cols cb0..+3 and 64+cb0..+3

    const float* qh = Q + ((size_t)h * SEQ + (size_t)qb * 128) * DK;
    const float* kh = K + (size_t)h * SEQ * DK;
    const float* vh = V + (size_t)h * SEQ * DK;

    // fill Q tile (natural layout)
    for (int idx = tid; idx < 128 * 16; idx += 256) {
        const int r  = idx >> 4;
        const int c4 = (idx & 15) << 2;
        *(float4*)&Qs[r * 68 + c4] = *(const float4*)(qh + r * 64 + c4);
    }

    float oacc[8][4] = {};
    float mrow[8], lrow[8];
#pragma unroll
    for (int i = 0; i < 8; ++i) { mrow[i] = -1e30f; lrow[i] = 0.f; }

    for (int kb = 0; kb <= qb; ++kb) {
        __syncthreads();   // prior reads of Kt/Vs/Ps done (also fences Qs on iter 0)

        // fill Kt (transposed) and Vs (natural)
        for (int idx = tid; idx < 2048; idx += 256) {
            const int kq = (idx & 7) + ((idx >> 10) << 3);   // 0..15 (quad idx)
            const int t  = (idx >> 3) & 127;                 // token 0..127
            float4 kv = *(const float4*)(kh + ((size_t)kb * 128 + t) * 64 + kq * 4);
            Kt[(4 * kq + 0) * 132 + t] = kv.x;
            Kt[(4 * kq + 1) * 132 + t] = kv.y;
            Kt[(4 * kq + 2) * 132 + t] = kv.z;
            Kt[(4 * kq + 3) * 132 + t] = kv.w;
            const int r  = idx >> 4;
            const int c4 = (idx & 15) << 2;
            *(float4*)&Vs[r * 68 + c4] =
                *(const float4*)(vh + ((size_t)kb * 128 + r) * 64 + c4);
        }
        __syncthreads();

        // S = Q K^T  (128x128x64)
        float sacc[8][8] = {};
#pragma unroll 4
        for (int d = 0; d < 64; ++d) {
            float qf[8], kf[8];
#pragma unroll
            for (int i = 0; i < 4; ++i) {
                qf[i]     = Qs[(rb0 + i) * 68 + d];
                qf[i + 4] = Qs[(64 + rb0 + i) * 68 + d];
            }
            *(float4*)&kf[0] = *(const float4*)&Kt[d * 132 + cb0];
            *(float4*)&kf[4] = *(const float4*)&Kt[d * 132 + 64 + cb0];
#pragma unroll
            for (int i = 0; i < 8; ++i)
#pragma unroll
                for (int j = 0; j < 8; ++j)
                    sacc[i][j] += qf[i] * kf[j];
        }

        const bool diag = (kb == qb);
#pragma unroll
        for (int i = 0; i < 8; ++i) {
            const int rl = (i < 4) ? (rb0 + i) : (64 + rb0 + i - 4);
#pragma unroll
            for (int j = 0; j < 8; ++j) {
                sacc[i][j] *= 0.125f;   // 1/sqrt(64)
                const int cl = (j < 4) ? (cb0 + j) : (64 + cb0 + j - 4);
                if (diag && cl > rl) sacc[i][j] = -1e30f;
            }
        }

        // online softmax per row (rows owned by 16-lane groups)
#pragma unroll
        for (int i = 0; i < 8; ++i) {
            float mt = sacc[i][0];
#pragma unroll
            for (int j = 1; j < 8; ++j) mt = fmaxf(mt, sacc[i][j]);
#pragma unroll
            for (int off = 1; off < 16; off <<= 1)
                mt = fmaxf(mt, __shfl_xor_sync(0xffffffffu, mt, off));
            const float mnew = fmaxf(mrow[i], mt);
            const float corr = __expf(mrow[i] - mnew);
            mrow[i] = mnew;
            float rs = 0.f;
#pragma unroll
            for (int j = 0; j < 8; ++j) {
                sacc[i][j] = __expf(sacc[i][j] - mnew);
                rs += sacc[i][j];
            }
#pragma unroll
            for (int off = 1; off < 16; off <<= 1)
                rs += __shfl_xor_sync(0xffffffffu, rs, off);
            lrow[i] = lrow[i] * corr + rs;
#pragma unroll
            for (int j = 0; j < 4; ++j) oacc[i][j] *= corr;
            const int rl = (i < 4) ? (rb0 + i) : (64 + rb0 + i - 4);
            *(float4*)&Ps[rl * 132 + cb0]      = *(float4*)&sacc[i][0];
            *(float4*)&Ps[rl * 132 + 64 + cb0] = *(float4*)&sacc[i][4];
        }
        __syncthreads();

        // O += P V  (128x64x128)
#pragma unroll 4
        for (int kk = 0; kk < 128; ++kk) {
            float pf[8], vf[4];
#pragma unroll
            for (int i = 0; i < 4; ++i) {
                pf[i]     = Ps[(rb0 + i) * 132 + kk];
                pf[i + 4] = Ps[(64 + rb0 + i) * 132 + kk];
            }
            *(float4*)&vf[0] = *(const float4*)&Vs[kk * 68 + cb0];
#pragma unroll
            for (int i = 0; i < 8; ++i)
#pragma unroll
                for (int j = 0; j < 4; ++j)
                    oacc[i][j] += pf[i] * vf[j];
        }
    }

    // normalize + store to [s, h*dk]
#pragma unroll
    for (int i = 0; i < 8; ++i) {
        const int rl = (i < 4) ? (rb0 + i) : (64 + rb0 + i - 4);
        const float inv = 1.f / lrow[i];
        const int m = qb * 128 + rl;
        float4* o = (float4*)(O + (size_t)m * DM + h * DK + cb0);
        *o = make_float4(oacc[i][0] * inv, oacc[i][1] * inv,
                         oacc[i][2] * inv, oacc[i][3] * inv);
    }
}

// ---------------------------------------------------------------------------
extern "C" void kernel_launch(void* const* d_in, const int* in_sizes, int n_in,
                              void* d_out, int out_size)
{
    const float* x  = (const float*)d_in[0];
    const float* Wq = (const float*)d_in[1];
    const float* Wk = (const float*)d_in[2];
    const float* Wv = (const float*)d_in[3];
    const float* Wo = (const float*)d_in[4];

    float *qp, *kp, *vp, *aop;
    cudaGetSymbolAddress((void**)&qp,  g_q);
    cudaGetSymbolAddress((void**)&kp,  g_k);
    cudaGetSymbolAddress((void**)&vp,  g_v);
    cudaGetSymbolAddress((void**)&aop, g_ao);

    dim3 gg(DM / 128, SEQ / 128);   // (8, 32)
    gemm_nt<2><<<gg, 256>>>(x, Wq, qp, SEQ, DM, DM);
    gemm_nt<2><<<gg, 256>>>(x, Wk, kp, SEQ, DM, DM);
    gemm_nt<1><<<gg, 256>>>(x, Wv, vp, SEQ, DM, DM);

    const size_t smem = (size_t)(128 * 68 + 64 * 132 + 128 * 68 + 128 * 132) * sizeof(float);
    cudaFuncSetAttribute(flash_attn, cudaFuncAttributeMaxDynamicSharedMemorySize, (int)smem);
    flash_attn<<<dim3(SEQ / 128, NH), 256, smem>>>(qp, kp, vp, aop);

    gemm_nt<0><<<gg, 256>>>(aop, Wo, (float*)d_out, SEQ, DM, DM);
}

// round 5
// speedup vs baseline: 2.5493x; 1.8432x over previous
#include <cuda_runtime.h>
#include <cuda_bf16.h>
#include <math.h>
#include <stdint.h>

#define SEQ 4096
#define DM  1024
#define NH  16
#define DK  64

// ---------------------------------------------------------------------------
// scratch (no allocs allowed) — all bf16 hi/lo pairs
// ---------------------------------------------------------------------------
__device__ __nv_bfloat16 g_xh [SEQ * DM];
__device__ __nv_bfloat16 g_xl [SEQ * DM];
__device__ __nv_bfloat16 g_wh [4][DM * DM];
__device__ __nv_bfloat16 g_wl [4][DM * DM];
__device__ __nv_bfloat16 g_qh [NH * SEQ * DK];
__device__ __nv_bfloat16 g_ql [NH * SEQ * DK];
__device__ __nv_bfloat16 g_kh [NH * SEQ * DK];
__device__ __nv_bfloat16 g_kl [NH * SEQ * DK];
__device__ __nv_bfloat16 g_vh [NH * SEQ * DK];
__device__ __nv_bfloat16 g_vl [NH * SEQ * DK];
__device__ __nv_bfloat16 g_aoh[SEQ * DM];
__device__ __nv_bfloat16 g_aol[SEQ * DM];

// ---------------------------------------------------------------------------
// helpers
// ---------------------------------------------------------------------------
static __device__ __forceinline__ uint32_t s2u(const void* p) {
    uint32_t a;
    asm("{ .reg .u64 t; cvta.to.shared.u64 t, %1; cvt.u32.u64 %0, t; }"
        : "=r"(a) : "l"(p));
    return a;
}
static __device__ __forceinline__ void ldsm4(uint32_t* r, uint32_t addr) {
    asm volatile("ldmatrix.sync.aligned.m8n8.x4.shared.b16 {%0,%1,%2,%3}, [%4];"
                 : "=r"(r[0]), "=r"(r[1]), "=r"(r[2]), "=r"(r[3]) : "r"(addr));
}
static __device__ __forceinline__ void mma16816(float* d, const uint32_t* a,
                                                uint32_t b0, uint32_t b1) {
    asm volatile(
        "mma.sync.aligned.m16n8k16.row.col.f32.bf16.bf16.f32 "
        "{%0,%1,%2,%3},{%4,%5,%6,%7},{%8,%9},{%0,%1,%2,%3};"
        : "+f"(d[0]), "+f"(d[1]), "+f"(d[2]), "+f"(d[3])
        : "r"(a[0]), "r"(a[1]), "r"(a[2]), "r"(a[3]), "r"(b0), "r"(b1));
}
static __device__ __forceinline__ void cp16(uint32_t s, const void* g) {
    asm volatile("cp.async.cg.shared.global [%0], [%1], 16;" :: "r"(s), "l"(g));
}
#define CP_COMMIT asm volatile("cp.async.commit_group;")
#define CP_WAIT0  asm volatile("cp.async.wait_group 0;")

static __device__ __forceinline__ uint32_t pack_bf2(__nv_bfloat16 a, __nv_bfloat16 b) {
    return (uint32_t)__bfloat16_as_ushort(a) | ((uint32_t)__bfloat16_as_ushort(b) << 16);
}

// ---------------------------------------------------------------------------
// split fp32 -> bf16 (hi, lo)
// ---------------------------------------------------------------------------
__global__ void __launch_bounds__(256)
split_bf16(const float* __restrict__ src, __nv_bfloat16* __restrict__ hi,
           __nv_bfloat16* __restrict__ lo, int n2)
{
    int i = blockIdx.x * 256 + threadIdx.x;
    if (i >= n2) return;
    float2 v = ((const float2*)src)[i];
    __nv_bfloat16 h0 = __float2bfloat16(v.x);
    __nv_bfloat16 h1 = __float2bfloat16(v.y);
    __nv_bfloat16 l0 = __float2bfloat16(v.x - __bfloat162float(h0));
    __nv_bfloat16 l1 = __float2bfloat16(v.y - __bfloat162float(h1));
    ((uint32_t*)hi)[i] = pack_bf2(h0, h1);
    ((uint32_t*)lo)[i] = pack_bf2(l0, l1);
}

// ---------------------------------------------------------------------------
// mma.sync bf16 split-3 GEMM: C[m,n] = sum_k A[m,k]*B[n,k], M=4096 N=K=1024
// 128x128x32 tiles, cp.async double-buffered, 8 warps (2m x 4n), warp 64x32.
// MODE 0: fp32 plain [M,N] to C.
// MODE 1: bf16 hi/lo head layout [h][s][dk] to Ch/Cl.
// MODE 2: RoPE + MODE 1.
// ---------------------------------------------------------------------------
template <int MODE>
__global__ void __launch_bounds__(256)
gemm_mma(const __nv_bfloat16* __restrict__ Ah_g, const __nv_bfloat16* __restrict__ Al_g,
         const __nv_bfloat16* __restrict__ Bh_g, const __nv_bfloat16* __restrict__ Bl_g,
         float* __restrict__ C, __nv_bfloat16* __restrict__ Ch, __nv_bfloat16* __restrict__ Cl)
{
    constexpr int K = DM;
    constexpr int TILE  = 10240;   // 128 rows x 40 bf16 (pitch 80B)
    constexpr int STAGE = 4 * TILE;
    extern __shared__ __align__(128) char smg[];
    const uint32_t sbase = s2u(smg);

    const int bm  = blockIdx.y * 128;
    const int bn  = blockIdx.x * 128;
    const int tid = threadIdx.x;
    const int lane = tid & 31;
    const int wid  = tid >> 5;
    const int wm = (wid >> 2) * 64;
    const int wn = (wid & 3) * 32;

    const __nv_bfloat16* srcs[4] = {
        Ah_g + (size_t)bm * K, Al_g + (size_t)bm * K,
        Bh_g + (size_t)bn * K, Bl_g + (size_t)bn * K };

    auto fill = [&](int s, int kc) {
#pragma unroll
        for (int t = 0; t < 4; ++t) {
#pragma unroll
            for (int i = 0; i < 2; ++i) {
                const int idx = i * 256 + tid;
                const int r = idx >> 2;
                const int c = idx & 3;
                cp16(sbase + s * STAGE + t * TILE + r * 80 + c * 16,
                     srcs[t] + (size_t)r * K + kc * 32 + c * 8);
            }
        }
        CP_COMMIT;
    };

    float acc[4][4][4] = {};

    fill(0, 0);
    for (int kc = 0; kc < K / 32; ++kc) {
        CP_WAIT0;
        __syncthreads();
        if (kc + 1 < K / 32) fill((kc + 1) & 1, kc + 1);

        const uint32_t aB = sbase + (kc & 1) * STAGE;
        const uint32_t bB = aB + 2 * TILE;
#pragma unroll
        for (int ks = 0; ks < 2; ++ks) {
            uint32_t ah[4][4], al[4][4], bh[2][4], bl[2][4];
#pragma unroll
            for (int mt = 0; mt < 4; ++mt) {
                const uint32_t ad = aB +
                    ((wm + mt * 16 + (lane & 15)) * 40 + ks * 16 + (lane >> 4) * 8) * 2;
                ldsm4(ah[mt], ad);
                ldsm4(al[mt], ad + TILE);
            }
#pragma unroll
            for (int np = 0; np < 2; ++np) {
                const uint32_t ad = bB +
                    ((wn + np * 16 + (lane & 15)) * 40 + ks * 16 + (lane >> 4) * 8) * 2;
                ldsm4(bh[np], ad);
                ldsm4(bl[np], ad + TILE);
            }
#pragma unroll
            for (int mt = 0; mt < 4; ++mt)
#pragma unroll
                for (int nt = 0; nt < 4; ++nt) {
                    const int np = nt >> 1, hf = nt & 1;
                    mma16816(acc[mt][nt], ah[mt], bh[np][hf], bh[np][hf + 2]);
                    mma16816(acc[mt][nt], ah[mt], bl[np][hf], bl[np][hf + 2]);
                    mma16816(acc[mt][nt], al[mt], bh[np][hf], bh[np][hf + 2]);
                }
        }
        __syncthreads();
    }

    // epilogue
#pragma unroll
    for (int mt = 0; mt < 4; ++mt)
#pragma unroll
        for (int ri = 0; ri < 2; ++ri) {
            const int m = bm + wm + mt * 16 + ri * 8 + (lane >> 2);
#pragma unroll
            for (int nt = 0; nt < 4; ++nt) {
                const int n = bn + wn + nt * 8 + 2 * (lane & 3);
                float v0 = acc[mt][nt][ri * 2 + 0];
                float v1 = acc[mt][nt][ri * 2 + 1];
                if (MODE == 0) {
                    *(float2*)(C + (size_t)m * DM + n) = make_float2(v0, v1);
                } else {
                    if (MODE == 2) {
                        const int d = n & 63;   // even
                        const float inv = powf(10000.f, -(float)d / 64.f);
                        float sn, cs;
                        sincosf((float)m * inv, &sn, &cs);
                        const float a = v0, b = v1;
                        v0 = a * cs - b * sn;
                        v1 = b * cs + a * sn;
                    }
                    const int hh = n >> 6;
                    const int d0 = n & 63;
                    const size_t off = ((size_t)hh * SEQ + m) * DK + d0;
                    __nv_bfloat16 h0 = __float2bfloat16(v0);
                    __nv_bfloat16 h1 = __float2bfloat16(v1);
                    __nv_bfloat16 l0 = __float2bfloat16(v0 - __bfloat162float(h0));
                    __nv_bfloat16 l1 = __float2bfloat16(v1 - __bfloat162float(h1));
                    *(uint32_t*)(Ch + off) = pack_bf2(h0, h1);
                    *(uint32_t*)(Cl + off) = pack_bf2(l0, l1);
                }
            }
        }
}

// ---------------------------------------------------------------------------
// mma.sync bf16 split-3 flash attention, causal.
// Block = (head, 128-q tile), 256 threads, 8 warps.
// S phase: warps 2(m)x4(n), warp 64x32 of S[128x128].
// PV phase: warps 2(m)x4(n over dk), warp 64x16 of O[128x64].
// Softmax row statistics reduced ACROSS the 4 column-warps via smem
// (redmax/redsum[4][128]) — all warps sharing a row keep identical (m, l).
// smem pitches: Q/K 72 bf16 (144B), Vt/P 136 bf16 (272B).
// ---------------------------------------------------------------------------
#define A_QH 0
#define A_QL 18432
#define A_KH 36864
#define A_KL 55296
#define A_VTH 73728
#define A_VTL 91136
#define A_PH 108544
#define A_PL 143360
#define A_RMAX 178176
#define A_RSUM 180224
#define A_TOT 182272

__global__ void __launch_bounds__(256)
flash_tc(const __nv_bfloat16* __restrict__ qh, const __nv_bfloat16* __restrict__ ql,
         const __nv_bfloat16* __restrict__ kh, const __nv_bfloat16* __restrict__ kl,
         const __nv_bfloat16* __restrict__ vh, const __nv_bfloat16* __restrict__ vl,
         __nv_bfloat16* __restrict__ aoh, __nv_bfloat16* __restrict__ aol)
{
    extern __shared__ __align__(128) char sma[];
    const uint32_t sbase = s2u(sma);
    float* redmax = (float*)(sma + A_RMAX);   // [4][128]
    float* redsum = (float*)(sma + A_RSUM);   // [4][128]

    const int h   = blockIdx.y;
    const int qb  = gridDim.x - 1 - blockIdx.x;   // heavy tiles first
    const int tid = threadIdx.x;
    const int lane = tid & 31;
    const int wid  = tid >> 5;
    const int wm  = (wid >> 2) * 64;
    const int wn4 = wid & 3;
    const int wn  = wn4 * 32;   // S-phase n offset (tokens)
    const int wno = wn4 * 16;   // PV-phase n offset (dk)

    const size_t hb = (size_t)h * SEQ * DK;

    // Q fill (cp.async): rows 128, 8 x 16B chunks per row, hi+lo
    {
        const __nv_bfloat16* qgh = qh + hb + (size_t)qb * 128 * DK;
        const __nv_bfloat16* qgl = ql + hb + (size_t)qb * 128 * DK;
#pragma unroll
        for (int i = 0; i < 4; ++i) {
            const int idx = i * 256 + tid;
            const int r = idx >> 3;
            const int c = idx & 7;
            cp16(sbase + A_QH + r * 144 + c * 16, qgh + r * 64 + c * 8);
            cp16(sbase + A_QL + r * 144 + c * 16, qgl + r * 64 + c * 8);
        }
        CP_COMMIT;
    }

    float oacc[4][2][4] = {};
    float mrow[4][2], lrow[4][2];
#pragma unroll
    for (int a = 0; a < 4; ++a)
#pragma unroll
        for (int b = 0; b < 2; ++b) { mrow[a][b] = -1e30f; lrow[a][b] = 0.f; }

    for (int kb = 0; kb <= qb; ++kb) {
        __syncthreads();   // prior-iter reads of K/Vt/P/red done

        // K fill via cp.async
        {
            const __nv_bfloat16* kgh = kh + hb + (size_t)kb * 128 * DK;
            const __nv_bfloat16* kgl = kl + hb + (size_t)kb * 128 * DK;
#pragma unroll
            for (int i = 0; i < 4; ++i) {
                const int idx = i * 256 + tid;
                const int r = idx >> 3;
                const int c = idx & 7;
                cp16(sbase + A_KH + r * 144 + c * 16, kgh + r * 64 + c * 8);
                cp16(sbase + A_KL + r * 144 + c * 16, kgl + r * 64 + c * 8);
            }
            CP_COMMIT;
        }
        // V transpose (manual): Vt[d][t], pitch 136
        {
            const uint32_t* vgh = (const uint32_t*)(vh + hb + (size_t)kb * 128 * DK);
            const uint32_t* vgl = (const uint32_t*)(vl + hb + (size_t)kb * 128 * DK);
            uint32_t* th = (uint32_t*)(sma + A_VTH);
            uint32_t* tl = (uint32_t*)(sma + A_VTL);
#pragma unroll
            for (int i = 0; i < 8; ++i) {
                const int idx = i * 256 + tid;
                const int tp = (idx & 7) | (((idx >> 5) & 7) << 3);   // 0..63
                const int j  = ((idx >> 3) & 3) | (((idx >> 8) & 7) << 2); // 0..31
                const int t  = tp * 2;
                uint32_t a = vgh[t * 32 + j];
                uint32_t b = vgh[(t + 1) * 32 + j];
                th[(2 * j) * 68 + tp]     = (a & 0xffffu) | (b << 16);
                th[(2 * j + 1) * 68 + tp] = (a >> 16) | (b & 0xffff0000u);
                a = vgl[t * 32 + j];
                b = vgl[(t + 1) * 32 + j];
                tl[(2 * j) * 68 + tp]     = (a & 0xffffu) | (b << 16);
                tl[(2 * j + 1) * 68 + tp] = (a >> 16) | (b & 0xffff0000u);
            }
        }
        CP_WAIT0;
        __syncthreads();

        // ---- S = Q K^T (3-term) ----
        float sacc[4][4][4] = {};
#pragma unroll
        for (int d16 = 0; d16 < 4; ++d16) {
            uint32_t ah[4][4], al[4][4], bh[2][4], bl[2][4];
#pragma unroll
            for (int mt = 0; mt < 4; ++mt) {
                const uint32_t ad = sbase + A_QH +
                    ((wm + mt * 16 + (lane & 15)) * 72 + d16 * 16 + (lane >> 4) * 8) * 2;
                ldsm4(ah[mt], ad);
                ldsm4(al[mt], ad + (A_QL - A_QH));
            }
#pragma unroll
            for (int np = 0; np < 2; ++np) {
                const uint32_t ad = sbase + A_KH +
                    ((wn + np * 16 + (lane & 15)) * 72 + d16 * 16 + (lane >> 4) * 8) * 2;
                ldsm4(bh[np], ad);
                ldsm4(bl[np], ad + (A_KL - A_KH));
            }
#pragma unroll
            for (int mt = 0; mt < 4; ++mt)
#pragma unroll
                for (int nt = 0; nt < 4; ++nt) {
                    const int np = nt >> 1, hf = nt & 1;
                    mma16816(sacc[mt][nt], ah[mt], bh[np][hf], bh[np][hf + 2]);
                    mma16816(sacc[mt][nt], ah[mt], bl[np][hf], bl[np][hf + 2]);
                    mma16816(sacc[mt][nt], al[mt], bh[np][hf], bh[np][hf + 2]);
                }
        }

        // ---- softmax pass 1: scale+mask, per-warp partial row max ----
        const bool diag = (kb == qb);
#pragma unroll
        for (int mt = 0; mt < 4; ++mt)
#pragma unroll
            for (int ri = 0; ri < 2; ++ri) {
                const int r = wm + mt * 16 + ri * 8 + (lane >> 2);   // local q row
                float vmax = -1e30f;
#pragma unroll
                for (int nt = 0; nt < 4; ++nt)
#pragma unroll
                    for (int ci = 0; ci < 2; ++ci) {
                        float v = sacc[mt][nt][ri * 2 + ci] * 0.125f;
                        if (diag) {
                            const int tc = wn + nt * 8 + 2 * (lane & 3) + ci;
                            if (tc > r) v = -1e30f;
                        }
                        sacc[mt][nt][ri * 2 + ci] = v;
                        vmax = fmaxf(vmax, v);
                    }
                vmax = fmaxf(vmax, __shfl_xor_sync(0xffffffffu, vmax, 1));
                vmax = fmaxf(vmax, __shfl_xor_sync(0xffffffffu, vmax, 2));
                if ((lane & 3) == 0) redmax[wn4 * 128 + r] = vmax;
            }
        __syncthreads();

        // ---- softmax pass 2: global max, exp, partial sums, P store ----
        float corrv[4][2];
#pragma unroll
        for (int mt = 0; mt < 4; ++mt)
#pragma unroll
            for (int ri = 0; ri < 2; ++ri) {
                const int r = wm + mt * 16 + ri * 8 + (lane >> 2);
                float gmax = fmaxf(fmaxf(redmax[r], redmax[128 + r]),
                                   fmaxf(redmax[256 + r], redmax[384 + r]));
                const float mnew = fmaxf(mrow[mt][ri], gmax);
                const float corr = __expf(mrow[mt][ri] - mnew);
                mrow[mt][ri] = mnew;
                corrv[mt][ri] = corr;
                float rs = 0.f;
#pragma unroll
                for (int nt = 0; nt < 4; ++nt)
#pragma unroll
                    for (int ci = 0; ci < 2; ++ci) {
                        const float p = __expf(sacc[mt][nt][ri * 2 + ci] - mnew);
                        sacc[mt][nt][ri * 2 + ci] = p;
                        rs += p;
                    }
                rs += __shfl_xor_sync(0xffffffffu, rs, 1);
                rs += __shfl_xor_sync(0xffffffffu, rs, 2);
                if ((lane & 3) == 0) redsum[wn4 * 128 + r] = rs;
#pragma unroll
                for (int ont = 0; ont < 2; ++ont) {
                    oacc[mt][ont][ri * 2 + 0] *= corr;
                    oacc[mt][ont][ri * 2 + 1] *= corr;
                }
                // write P hi/lo
#pragma unroll
                for (int nt = 0; nt < 4; ++nt) {
                    const float p0 = sacc[mt][nt][ri * 2 + 0];
                    const float p1 = sacc[mt][nt][ri * 2 + 1];
                    __nv_bfloat16 h0 = __float2bfloat16(p0);
                    __nv_bfloat16 h1 = __float2bfloat16(p1);
                    __nv_bfloat16 l0 = __float2bfloat16(p0 - __bfloat162float(h0));
                    __nv_bfloat16 l1 = __float2bfloat16(p1 - __bfloat162float(h1));
                    const int colP = wn + nt * 8 + 2 * (lane & 3);
                    const uint32_t boff = (uint32_t)(r * 136 + colP) * 2;
                    *(uint32_t*)(sma + A_PH + boff) = pack_bf2(h0, h1);
                    *(uint32_t*)(sma + A_PL + boff) = pack_bf2(l0, l1);
                }
            }
        __syncthreads();

        // ---- softmax pass 3: global row sums ----
#pragma unroll
        for (int mt = 0; mt < 4; ++mt)
#pragma unroll
            for (int ri = 0; ri < 2; ++ri) {
                const int r = wm + mt * 16 + ri * 8 + (lane >> 2);
                const float rsg = redsum[r] + redsum[128 + r] +
                                  redsum[256 + r] + redsum[384 + r];
                lrow[mt][ri] = lrow[mt][ri] * corrv[mt][ri] + rsg;
            }

        // ---- O += P V (3-term) ----
#pragma unroll
        for (int kt = 0; kt < 8; ++kt) {
            uint32_t ah[4][4], al[4][4], bh[4], bl[4];
#pragma unroll
            for (int mt = 0; mt < 4; ++mt) {
                const uint32_t ad = sbase + A_PH +
                    ((wm + mt * 16 + (lane & 15)) * 136 + kt * 16 + (lane >> 4) * 8) * 2;
                ldsm4(ah[mt], ad);
                ldsm4(al[mt], ad + (A_PL - A_PH));
            }
            {
                const uint32_t ad = sbase + A_VTH +
                    ((wno + (lane & 15)) * 136 + kt * 16 + (lane >> 4) * 8) * 2;
                ldsm4(bh, ad);
                ldsm4(bl, ad + (A_VTL - A_VTH));
            }
#pragma unroll
            for (int mt = 0; mt < 4; ++mt)
#pragma unroll
                for (int ont = 0; ont < 2; ++ont) {
                    mma16816(oacc[mt][ont], ah[mt], bh[ont], bh[ont + 2]);
                    mma16816(oacc[mt][ont], ah[mt], bl[ont], bl[ont + 2]);
                    mma16816(oacc[mt][ont], al[mt], bh[ont], bh[ont + 2]);
                }
        }
    }

    // epilogue: normalize, split to bf16 hi/lo, store [s][dm]
#pragma unroll
    for (int mt = 0; mt < 4; ++mt)
#pragma unroll
        for (int ri = 0; ri < 2; ++ri) {
            const float inv = 1.f / lrow[mt][ri];
            const int q = qb * 128 + wm + mt * 16 + ri * 8 + (lane >> 2);
#pragma unroll
            for (int ont = 0; ont < 2; ++ont) {
                const float v0 = oacc[mt][ont][ri * 2 + 0] * inv;
                const float v1 = oacc[mt][ont][ri * 2 + 1] * inv;
                const int col = h * 64 + wno + ont * 8 + 2 * (lane & 3);
                __nv_bfloat16 h0 = __float2bfloat16(v0);
                __nv_bfloat16 h1 = __float2bfloat16(v1);
                __nv_bfloat16 l0 = __float2bfloat16(v0 - __bfloat162float(h0));
                __nv_bfloat16 l1 = __float2bfloat16(v1 - __bfloat162float(h1));
                *(uint32_t*)(aoh + (size_t)q * DM + col) = pack_bf2(h0, h1);
                *(uint32_t*)(aol + (size_t)q * DM + col) = pack_bf2(l0, l1);
            }
        }
}

// ---------------------------------------------------------------------------
extern "C" void kernel_launch(void* const* d_in, const int* in_sizes, int n_in,
                              void* d_out, int out_size)
{
    const float* x  = (const float*)d_in[0];
    const float* Wq = (const float*)d_in[1];
    const float* Wk = (const float*)d_in[2];
    const float* Wv = (const float*)d_in[3];
    const float* Wo = (const float*)d_in[4];

    __nv_bfloat16 *xh, *xl, *wh, *wl, *qhp, *qlp, *khp, *klp, *vhp, *vlp, *aoh, *aol;
    cudaGetSymbolAddress((void**)&xh,  g_xh);
    cudaGetSymbolAddress((void**)&xl,  g_xl);
    cudaGetSymbolAddress((void**)&wh,  g_wh);
    cudaGetSymbolAddress((void**)&wl,  g_wl);
    cudaGetSymbolAddress((void**)&qhp, g_qh);
    cudaGetSymbolAddress((void**)&qlp, g_ql);
    cudaGetSymbolAddress((void**)&khp, g_kh);
    cudaGetSymbolAddress((void**)&klp, g_kl);
    cudaGetSymbolAddress((void**)&vhp, g_vh);
    cudaGetSymbolAddress((void**)&vlp, g_vl);
    cudaGetSymbolAddress((void**)&aoh, g_aoh);
    cudaGetSymbolAddress((void**)&aol, g_aol);

    const int nx2 = SEQ * DM / 2;
    const int nw2 = DM * DM / 2;
    split_bf16<<<(nx2 + 255) / 256, 256>>>(x, xh, xl, nx2);
    split_bf16<<<(nw2 + 255) / 256, 256>>>(Wq, wh + 0 * (size_t)DM * DM, wl + 0 * (size_t)DM * DM, nw2);
    split_bf16<<<(nw2 + 255) / 256, 256>>>(Wk, wh + 1 * (size_t)DM * DM, wl + 1 * (size_t)DM * DM, nw2);
    split_bf16<<<(nw2 + 255) / 256, 256>>>(Wv, wh + 2 * (size_t)DM * DM, wl + 2 * (size_t)DM * DM, nw2);
    split_bf16<<<(nw2 + 255) / 256, 256>>>(Wo, wh + 3 * (size_t)DM * DM, wl + 3 * (size_t)DM * DM, nw2);

    const int gsm = 2 * 4 * 10240;   // 81,920 B
    cudaFuncSetAttribute(gemm_mma<0>, cudaFuncAttributeMaxDynamicSharedMemorySize, gsm);
    cudaFuncSetAttribute(gemm_mma<1>, cudaFuncAttributeMaxDynamicSharedMemorySize, gsm);
    cudaFuncSetAttribute(gemm_mma<2>, cudaFuncAttributeMaxDynamicSharedMemorySize, gsm);
    cudaFuncSetAttribute(flash_tc, cudaFuncAttributeMaxDynamicSharedMemorySize, A_TOT);

    dim3 gg(DM / 128, SEQ / 128);   // (8, 32)
    gemm_mma<2><<<gg, 256, gsm>>>(xh, xl, wh + 0 * (size_t)DM * DM, wl + 0 * (size_t)DM * DM,
                                  nullptr, qhp, qlp);
    gemm_mma<2><<<gg, 256, gsm>>>(xh, xl, wh + 1 * (size_t)DM * DM, wl + 1 * (size_t)DM * DM,
                                  nullptr, khp, klp);
    gemm_mma<1><<<gg, 256, gsm>>>(xh, xl, wh + 2 * (size_t)DM * DM, wl + 2 * (size_t)DM * DM,
                                  nullptr, vhp, vlp);

    flash_tc<<<dim3(SEQ / 128, NH), 256, A_TOT>>>(qhp, qlp, khp, klp, vhp, vlp, aoh, aol);

    gemm_mma<0><<<gg, 256, gsm>>>(aoh, aol, wh + 3 * (size_t)DM * DM, wl + 3 * (size_t)DM * DM,
                                  (float*)d_out, nullptr, nullptr);
}

// round 6
// speedup vs baseline: 2.9134x; 1.1428x over previous
#include <cuda_runtime.h>
#include <cuda_bf16.h>
#include <math.h>
#include <stdint.h>

#define SEQ 4096
#define DM  1024
#define NH  16
#define DK  64

// ---------------------------------------------------------------------------
// scratch (no allocs allowed) — all bf16 hi/lo pairs
// ---------------------------------------------------------------------------
__device__ __nv_bfloat16 g_xh [SEQ * DM];
__device__ __nv_bfloat16 g_xl [SEQ * DM];
__device__ __nv_bfloat16 g_wh [4][DM * DM];
__device__ __nv_bfloat16 g_wl [4][DM * DM];
__device__ __nv_bfloat16 g_qh [NH * SEQ * DK];
__device__ __nv_bfloat16 g_ql [NH * SEQ * DK];
__device__ __nv_bfloat16 g_kh [NH * SEQ * DK];
__device__ __nv_bfloat16 g_kl [NH * SEQ * DK];
__device__ __nv_bfloat16 g_vh [NH * SEQ * DK];
__device__ __nv_bfloat16 g_vl [NH * SEQ * DK];
__device__ __nv_bfloat16 g_aoh[SEQ * DM];
__device__ __nv_bfloat16 g_aol[SEQ * DM];

// ---------------------------------------------------------------------------
// helpers
// ---------------------------------------------------------------------------
static __device__ __forceinline__ uint32_t s2u(const void* p) {
    uint32_t a;
    asm("{ .reg .u64 t; cvta.to.shared.u64 t, %1; cvt.u32.u64 %0, t; }"
        : "=r"(a) : "l"(p));
    return a;
}
static __device__ __forceinline__ void ldsm4(uint32_t* r, uint32_t addr) {
    asm volatile("ldmatrix.sync.aligned.m8n8.x4.shared.b16 {%0,%1,%2,%3}, [%4];"
                 : "=r"(r[0]), "=r"(r[1]), "=r"(r[2]), "=r"(r[3]) : "r"(addr));
}
static __device__ __forceinline__ void ldsm4t(uint32_t* r, uint32_t addr) {
    asm volatile("ldmatrix.sync.aligned.m8n8.x4.trans.shared.b16 {%0,%1,%2,%3}, [%4];"
                 : "=r"(r[0]), "=r"(r[1]), "=r"(r[2]), "=r"(r[3]) : "r"(addr));
}
static __device__ __forceinline__ void mma16816(float* d, const uint32_t* a,
                                                uint32_t b0, uint32_t b1) {
    asm volatile(
        "mma.sync.aligned.m16n8k16.row.col.f32.bf16.bf16.f32 "
        "{%0,%1,%2,%3},{%4,%5,%6,%7},{%8,%9},{%0,%1,%2,%3};"
        : "+f"(d[0]), "+f"(d[1]), "+f"(d[2]), "+f"(d[3])
        : "r"(a[0]), "r"(a[1]), "r"(a[2]), "r"(a[3]), "r"(b0), "r"(b1));
}
static __device__ __forceinline__ void cp16(uint32_t s, const void* g) {
    asm volatile("cp.async.cg.shared.global [%0], [%1], 16;" :: "r"(s), "l"(g));
}
#define CP_COMMIT asm volatile("cp.async.commit_group;")
#define CP_WAIT0  asm volatile("cp.async.wait_group 0;")
#define CP_WAIT1  asm volatile("cp.async.wait_group 1;")
#define CP_WAIT2  asm volatile("cp.async.wait_group 2;")

static __device__ __forceinline__ uint32_t pack_bf2(__nv_bfloat16 a, __nv_bfloat16 b) {
    return (uint32_t)__bfloat16_as_ushort(a) | ((uint32_t)__bfloat16_as_ushort(b) << 16);
}

// ---------------------------------------------------------------------------
// split fp32 -> bf16 (hi, lo): x (1 launch) and the 4 weights (1 launch)
// ---------------------------------------------------------------------------
__global__ void __launch_bounds__(256)
split_bf16(const float* __restrict__ src, __nv_bfloat16* __restrict__ hi,
           __nv_bfloat16* __restrict__ lo, int n2)
{
    int i = blockIdx.x * 256 + threadIdx.x;
    if (i >= n2) return;
    float2 v = ((const float2*)src)[i];
    __nv_bfloat16 h0 = __float2bfloat16(v.x);
    __nv_bfloat16 h1 = __float2bfloat16(v.y);
    __nv_bfloat16 l0 = __float2bfloat16(v.x - __bfloat162float(h0));
    __nv_bfloat16 l1 = __float2bfloat16(v.y - __bfloat162float(h1));
    ((uint32_t*)hi)[i] = pack_bf2(h0, h1);
    ((uint32_t*)lo)[i] = pack_bf2(l0, l1);
}

__global__ void __launch_bounds__(256)
split4_bf16(const float* __restrict__ s0, const float* __restrict__ s1,
            const float* __restrict__ s2, const float* __restrict__ s3,
            __nv_bfloat16* __restrict__ hi, __nv_bfloat16* __restrict__ lo, int n2)
{
    int i = blockIdx.x * 256 + threadIdx.x;
    if (i >= n2) return;
    const int y = blockIdx.y;
    const float* s = (y == 0) ? s0 : (y == 1) ? s1 : (y == 2) ? s2 : s3;
    float2 v = ((const float2*)s)[i];
    __nv_bfloat16 h0 = __float2bfloat16(v.x);
    __nv_bfloat16 h1 = __float2bfloat16(v.y);
    __nv_bfloat16 l0 = __float2bfloat16(v.x - __bfloat162float(h0));
    __nv_bfloat16 l1 = __float2bfloat16(v.y - __bfloat162float(h1));
    const size_t base = (size_t)y * (DM * DM / 2);
    ((uint32_t*)hi)[base + i] = pack_bf2(h0, h1);
    ((uint32_t*)lo)[base + i] = pack_bf2(l0, l1);
}

// ---------------------------------------------------------------------------
// mma.sync bf16 split-3 GEMM: C[m,n] = sum_k A[m,k]*B[n,k], M=4096 N=K=1024
// 128x128x32 tiles, cp.async double-buffered, 8 warps (2m x 4n), warp 64x32.
// qkv != 0: blockIdx.z selects weight z and output (z<2: RoPE+head bf16 hi/lo;
//           z==2: head layout bf16 hi/lo).
// qkv == 0: plain fp32 [M,N] to C using weight 3 (Wo).
// ---------------------------------------------------------------------------
__global__ void __launch_bounds__(256)
gemm_mma(const __nv_bfloat16* __restrict__ Ah_g, const __nv_bfloat16* __restrict__ Al_g,
         const __nv_bfloat16* __restrict__ WhAll, const __nv_bfloat16* __restrict__ WlAll,
         float* __restrict__ C,
         __nv_bfloat16* __restrict__ C0h, __nv_bfloat16* __restrict__ C0l,
         __nv_bfloat16* __restrict__ C1h, __nv_bfloat16* __restrict__ C1l,
         __nv_bfloat16* __restrict__ C2h, __nv_bfloat16* __restrict__ C2l,
         int qkv)
{
    constexpr int K = DM;
    constexpr int TILE  = 10240;   // 128 rows x 40 bf16 (pitch 80B)
    constexpr int STAGE = 4 * TILE;
    extern __shared__ __align__(128) char smg[];
    const uint32_t sbase = s2u(smg);

    const int z   = blockIdx.z;
    const int mode = qkv ? ((z == 2) ? 1 : 2) : 0;   // 1: head, 2: rope+head, 0: plain
    const size_t wsel = qkv ? (size_t)z * DM * DM : (size_t)3 * DM * DM;
    const __nv_bfloat16* Bh_g = WhAll + wsel;
    const __nv_bfloat16* Bl_g = WlAll + wsel;
    __nv_bfloat16* Ch = (z == 0) ? C0h : (z == 1) ? C1h : C2h;
    __nv_bfloat16* Cl = (z == 0) ? C0l : (z == 1) ? C1l : C2l;

    const int bm  = blockIdx.y * 128;
    const int bn  = blockIdx.x * 128;
    const int tid = threadIdx.x;
    const int lane = tid & 31;
    const int wid  = tid >> 5;
    const int wm = (wid >> 2) * 64;
    const int wn = (wid & 3) * 32;

    const __nv_bfloat16* srcs[4] = {
        Ah_g + (size_t)bm * K, Al_g + (size_t)bm * K,
        Bh_g + (size_t)bn * K, Bl_g + (size_t)bn * K };

    auto fill = [&](int s, int kc) {
#pragma unroll
        for (int t = 0; t < 4; ++t) {
#pragma unroll
            for (int i = 0; i < 2; ++i) {
                const int idx = i * 256 + tid;
                const int r = idx >> 2;
                const int c = idx & 3;
                cp16(sbase + s * STAGE + t * TILE + r * 80 + c * 16,
                     srcs[t] + (size_t)r * K + kc * 32 + c * 8);
            }
        }
        CP_COMMIT;
    };

    float acc[4][4][4] = {};

    fill(0, 0);
    for (int kc = 0; kc < K / 32; ++kc) {
        CP_WAIT0;
        __syncthreads();
        if (kc + 1 < K / 32) fill((kc + 1) & 1, kc + 1);

        const uint32_t aB = sbase + (kc & 1) * STAGE;
        const uint32_t bB = aB + 2 * TILE;
#pragma unroll
        for (int ks = 0; ks < 2; ++ks) {
            uint32_t ah[4][4], al[4][4], bh[2][4], bl[2][4];
#pragma unroll
            for (int mt = 0; mt < 4; ++mt) {
                const uint32_t ad = aB +
                    ((wm + mt * 16 + (lane & 15)) * 40 + ks * 16 + (lane >> 4) * 8) * 2;
                ldsm4(ah[mt], ad);
                ldsm4(al[mt], ad + TILE);
            }
#pragma unroll
            for (int np = 0; np < 2; ++np) {
                const uint32_t ad = bB +
                    ((wn + np * 16 + (lane & 15)) * 40 + ks * 16 + (lane >> 4) * 8) * 2;
                ldsm4(bh[np], ad);
                ldsm4(bl[np], ad + TILE);
            }
#pragma unroll
            for (int mt = 0; mt < 4; ++mt)
#pragma unroll
                for (int nt = 0; nt < 4; ++nt) {
                    const int np = nt >> 1, hf = nt & 1;
                    mma16816(acc[mt][nt], ah[mt], bh[np][hf], bh[np][hf + 2]);
                    mma16816(acc[mt][nt], ah[mt], bl[np][hf], bl[np][hf + 2]);
                    mma16816(acc[mt][nt], al[mt], bh[np][hf], bh[np][hf + 2]);
                }
        }
        __syncthreads();
    }

    // epilogue
#pragma unroll
    for (int mt = 0; mt < 4; ++mt)
#pragma unroll
        for (int ri = 0; ri < 2; ++ri) {
            const int m = bm + wm + mt * 16 + ri * 8 + (lane >> 2);
#pragma unroll
            for (int nt = 0; nt < 4; ++nt) {
                const int n = bn + wn + nt * 8 + 2 * (lane & 3);
                float v0 = acc[mt][nt][ri * 2 + 0];
                float v1 = acc[mt][nt][ri * 2 + 1];
                if (mode == 0) {
                    *(float2*)(C + (size_t)m * DM + n) = make_float2(v0, v1);
                } else {
                    if (mode == 2) {
                        const int d = n & 63;   // even
                        const float inv = powf(10000.f, -(float)d / 64.f);
                        float sn, cs;
                        sincosf((float)m * inv, &sn, &cs);
                        const float a = v0, b = v1;
                        v0 = a * cs - b * sn;
                        v1 = b * cs + a * sn;
                    }
                    const int hh = n >> 6;
                    const int d0 = n & 63;
                    const size_t off = ((size_t)hh * SEQ + m) * DK + d0;
                    __nv_bfloat16 h0 = __float2bfloat16(v0);
                    __nv_bfloat16 h1 = __float2bfloat16(v1);
                    __nv_bfloat16 l0 = __float2bfloat16(v0 - __bfloat162float(h0));
                    __nv_bfloat16 l1 = __float2bfloat16(v1 - __bfloat162float(h1));
                    *(uint32_t*)(Ch + off) = pack_bf2(h0, h1);
                    *(uint32_t*)(Cl + off) = pack_bf2(l0, l1);
                }
            }
        }
}

// ---------------------------------------------------------------------------
// mma.sync bf16 split-3 flash attention, causal.
// Block = (head, 128-q tile), 256 threads, 8 warps.
// K double-buffered; V natural layout, PV B-fragments via ldmatrix.trans.
// V(kb) + K(kb+1) cp.async issued at loop top; S-phase overlaps the loads.
// Softmax row stats reduced across the 4 column-warps via smem.
// pitches: Q/K/V 72 bf16 (144B), P 136 bf16 (272B) — ldmatrix conflict-free.
// ---------------------------------------------------------------------------
#define A_QH   0
#define A_QL   18432
#define A_KH0  36864
#define A_KH1  73728
#define A_VH   110592
#define A_VL   129024
#define A_PH   147456
#define A_PL   182272
#define A_RMAX 217088
#define A_RSUM 219136
#define A_TOT  221184

__global__ void __launch_bounds__(256)
flash_tc(const __nv_bfloat16* __restrict__ qh, const __nv_bfloat16* __restrict__ ql,
         const __nv_bfloat16* __restrict__ kh, const __nv_bfloat16* __restrict__ kl,
         const __nv_bfloat16* __restrict__ vh, const __nv_bfloat16* __restrict__ vl,
         __nv_bfloat16* __restrict__ aoh, __nv_bfloat16* __restrict__ aol)
{
    extern __shared__ __align__(128) char sma[];
    const uint32_t sbase = s2u(sma);
    float* redmax = (float*)(sma + A_RMAX);   // [4][128]
    float* redsum = (float*)(sma + A_RSUM);   // [4][128]

    const int h   = blockIdx.y;
    const int qb  = gridDim.x - 1 - blockIdx.x;   // heavy tiles first
    const int tid = threadIdx.x;
    const int lane = tid & 31;
    const int wid  = tid >> 5;
    const int wm  = (wid >> 2) * 64;
    const int wn4 = wid & 3;
    const int wn  = wn4 * 32;   // S-phase n offset (tokens)
    const int wno = wn4 * 16;   // PV-phase n offset (dk)

    const size_t hb = (size_t)h * SEQ * DK;

    // prologue: Q + K(0) cp.async (one group)
    {
        const __nv_bfloat16* qgh = qh + hb + (size_t)qb * 128 * DK;
        const __nv_bfloat16* qgl = ql + hb + (size_t)qb * 128 * DK;
        const __nv_bfloat16* kgh = kh + hb;
        const __nv_bfloat16* kgl = kl + hb;
#pragma unroll
        for (int i = 0; i < 4; ++i) {
            const int idx = i * 256 + tid;
            const int r = idx >> 3;
            const int c = idx & 7;
            cp16(sbase + A_QH + r * 144 + c * 16, qgh + r * 64 + c * 8);
            cp16(sbase + A_QL + r * 144 + c * 16, qgl + r * 64 + c * 8);
            cp16(sbase + A_KH0 + r * 144 + c * 16, kgh + r * 64 + c * 8);
            cp16(sbase + A_KH0 + 18432 + r * 144 + c * 16, kgl + r * 64 + c * 8);
        }
        CP_COMMIT;
    }

    float oacc[4][2][4] = {};
    float mrow[4][2], lrow[4][2];
#pragma unroll
    for (int a = 0; a < 4; ++a)
#pragma unroll
        for (int b = 0; b < 2; ++b) { mrow[a][b] = -1e30f; lrow[a][b] = 0.f; }

    for (int kb = 0; kb <= qb; ++kb) {
        __syncthreads();   // prior-iter reads of V/P/red done

        // issue V(kb) (group), then K(kb+1) prefetch into alt buffer (group)
        {
            const __nv_bfloat16* vgh = vh + hb + (size_t)kb * 128 * DK;
            const __nv_bfloat16* vgl = vl + hb + (size_t)kb * 128 * DK;
#pragma unroll
            for (int i = 0; i < 4; ++i) {
                const int idx = i * 256 + tid;
                const int r = idx >> 3;
                const int c = idx & 7;
                cp16(sbase + A_VH + r * 144 + c * 16, vgh + r * 64 + c * 8);
                cp16(sbase + A_VL + r * 144 + c * 16, vgl + r * 64 + c * 8);
            }
            CP_COMMIT;
        }
        if (kb < qb) {
            const __nv_bfloat16* kgh = kh + hb + (size_t)(kb + 1) * 128 * DK;
            const __nv_bfloat16* kgl = kl + hb + (size_t)(kb + 1) * 128 * DK;
            const uint32_t kB = sbase + (((kb + 1) & 1) ? A_KH1 : A_KH0);
#pragma unroll
            for (int i = 0; i < 4; ++i) {
                const int idx = i * 256 + tid;
                const int r = idx >> 3;
                const int c = idx & 7;
                cp16(kB + r * 144 + c * 16, kgh + r * 64 + c * 8);
                cp16(kB + 18432 + r * 144 + c * 16, kgl + r * 64 + c * 8);
            }
        }
        CP_COMMIT;

        CP_WAIT2;          // K(kb) (+Q on first iter) resident
        __syncthreads();

        const uint32_t kBuf = sbase + ((kb & 1) ? A_KH1 : A_KH0);

        // ---- S = Q K^T (3-term) ----
        float sacc[4][4][4] = {};
#pragma unroll
        for (int d16 = 0; d16 < 4; ++d16) {
            uint32_t ah[4][4], al[4][4], bh[2][4], bl[2][4];
#pragma unroll
            for (int mt = 0; mt < 4; ++mt) {
                const uint32_t ad = sbase + A_QH +
                    ((wm + mt * 16 + (lane & 15)) * 72 + d16 * 16 + (lane >> 4) * 8) * 2;
                ldsm4(ah[mt], ad);
                ldsm4(al[mt], ad + (A_QL - A_QH));
            }
#pragma unroll
            for (int np = 0; np < 2; ++np) {
                const uint32_t ad = kBuf +
                    ((wn + np * 16 + (lane & 15)) * 72 + d16 * 16 + (lane >> 4) * 8) * 2;
                ldsm4(bh[np], ad);
                ldsm4(bl[np], ad + 18432);
            }
#pragma unroll
            for (int mt = 0; mt < 4; ++mt)
#pragma unroll
                for (int nt = 0; nt < 4; ++nt) {
                    const int np = nt >> 1, hf = nt & 1;
                    mma16816(sacc[mt][nt], ah[mt], bh[np][hf], bh[np][hf + 2]);
                    mma16816(sacc[mt][nt], ah[mt], bl[np][hf], bl[np][hf + 2]);
                    mma16816(sacc[mt][nt], al[mt], bh[np][hf], bh[np][hf + 2]);
                }
        }

        // ---- softmax pass 1: scale+mask, per-warp partial row max ----
        const bool diag = (kb == qb);
#pragma unroll
        for (int mt = 0; mt < 4; ++mt)
#pragma unroll
            for (int ri = 0; ri < 2; ++ri) {
                const int r = wm + mt * 16 + ri * 8 + (lane >> 2);   // local q row
                float vmax = -1e30f;
#pragma unroll
                for (int nt = 0; nt < 4; ++nt)
#pragma unroll
                    for (int ci = 0; ci < 2; ++ci) {
                        float v = sacc[mt][nt][ri * 2 + ci] * 0.125f;
                        if (diag) {
                            const int tc = wn + nt * 8 + 2 * (lane & 3) + ci;
                            if (tc > r) v = -1e30f;
                        }
                        sacc[mt][nt][ri * 2 + ci] = v;
                        vmax = fmaxf(vmax, v);
                    }
                vmax = fmaxf(vmax, __shfl_xor_sync(0xffffffffu, vmax, 1));
                vmax = fmaxf(vmax, __shfl_xor_sync(0xffffffffu, vmax, 2));
                if ((lane & 3) == 0) redmax[wn4 * 128 + r] = vmax;
            }
        __syncthreads();

        // ---- softmax pass 2: global max, exp, partial sums, P store ----
        float corrv[4][2];
#pragma unroll
        for (int mt = 0; mt < 4; ++mt)
#pragma unroll
            for (int ri = 0; ri < 2; ++ri) {
                const int r = wm + mt * 16 + ri * 8 + (lane >> 2);
                float gmax = fmaxf(fmaxf(redmax[r], redmax[128 + r]),
                                   fmaxf(redmax[256 + r], redmax[384 + r]));
                const float mnew = fmaxf(mrow[mt][ri], gmax);
                const float corr = __expf(mrow[mt][ri] - mnew);
                mrow[mt][ri] = mnew;
                corrv[mt][ri] = corr;
                float rs = 0.f;
#pragma unroll
                for (int nt = 0; nt < 4; ++nt)
#pragma unroll
                    for (int ci = 0; ci < 2; ++ci) {
                        const float p = __expf(sacc[mt][nt][ri * 2 + ci] - mnew);
                        sacc[mt][nt][ri * 2 + ci] = p;
                        rs += p;
                    }
                rs += __shfl_xor_sync(0xffffffffu, rs, 1);
                rs += __shfl_xor_sync(0xffffffffu, rs, 2);
                if ((lane & 3) == 0) redsum[wn4 * 128 + r] = rs;
#pragma unroll
                for (int ont = 0; ont < 2; ++ont) {
                    oacc[mt][ont][ri * 2 + 0] *= corr;
                    oacc[mt][ont][ri * 2 + 1] *= corr;
                }
                // write P hi/lo
#pragma unroll
                for (int nt = 0; nt < 4; ++nt) {
                    const float p0 = sacc[mt][nt][ri * 2 + 0];
                    const float p1 = sacc[mt][nt][ri * 2 + 1];
                    __nv_bfloat16 h0 = __float2bfloat16(p0);
                    __nv_bfloat16 h1 = __float2bfloat16(p1);
                    __nv_bfloat16 l0 = __float2bfloat16(p0 - __bfloat162float(h0));
                    __nv_bfloat16 l1 = __float2bfloat16(p1 - __bfloat162float(h1));
                    const int colP = wn + nt * 8 + 2 * (lane & 3);
                    const uint32_t boff = (uint32_t)(r * 136 + colP) * 2;
                    *(uint32_t*)(sma + A_PH + boff) = pack_bf2(h0, h1);
                    *(uint32_t*)(sma + A_PL + boff) = pack_bf2(l0, l1);
                }
            }
        CP_WAIT1;          // V(kb) resident (K(kb+1) may still be in flight)
        __syncthreads();

        // ---- softmax pass 3: global row sums ----
#pragma unroll
        for (int mt = 0; mt < 4; ++mt)
#pragma unroll
            for (int ri = 0; ri < 2; ++ri) {
                const int r = wm + mt * 16 + ri * 8 + (lane >> 2);
                const float rsg = redsum[r] + redsum[128 + r] +
                                  redsum[256 + r] + redsum[384 + r];
                lrow[mt][ri] = lrow[mt][ri] * corrv[mt][ri] + rsg;
            }

        // ---- O += P V (3-term), V B-frags via ldmatrix.trans ----
#pragma unroll
        for (int kt = 0; kt < 8; ++kt) {
            uint32_t ah[4][4], al[4][4], bh[4], bl[4];
#pragma unroll
            for (int mt = 0; mt < 4; ++mt) {
                const uint32_t ad = sbase + A_PH +
                    ((wm + mt * 16 + (lane & 15)) * 136 + kt * 16 + (lane >> 4) * 8) * 2;
                ldsm4(ah[mt], ad);
                ldsm4(al[mt], ad + (A_PL - A_PH));
            }
            {
                const int t_loc = kt * 16 + (lane & 7) + ((lane >> 3) & 1) * 8;
                const int d_loc = wno + ((lane >> 4) & 1) * 8;
                const uint32_t ad = sbase + A_VH + (uint32_t)(t_loc * 72 + d_loc) * 2;
                ldsm4t(bh, ad);
                ldsm4t(bl, ad + (A_VL - A_VH));
            }
#pragma unroll
            for (int mt = 0; mt < 4; ++mt)
#pragma unroll
                for (int ont = 0; ont < 2; ++ont) {
                    mma16816(oacc[mt][ont], ah[mt], bh[2 * ont], bh[2 * ont + 1]);
                    mma16816(oacc[mt][ont], ah[mt], bl[2 * ont], bl[2 * ont + 1]);
                    mma16816(oacc[mt][ont], al[mt], bh[2 * ont], bh[2 * ont + 1]);
                }
        }
    }

    // epilogue: normalize, split to bf16 hi/lo, store [s][dm]
#pragma unroll
    for (int mt = 0; mt < 4; ++mt)
#pragma unroll
        for (int ri = 0; ri < 2; ++ri) {
            const float inv = 1.f / lrow[mt][ri];
            const int q = qb * 128 + wm + mt * 16 + ri * 8 + (lane >> 2);
#pragma unroll
            for (int ont = 0; ont < 2; ++ont) {
                const float v0 = oacc[mt][ont][ri * 2 + 0] * inv;
                const float v1 = oacc[mt][ont][ri * 2 + 1] * inv;
                const int col = h * 64 + wno + ont * 8 + 2 * (lane & 3);
                __nv_bfloat16 h0 = __float2bfloat16(v0);
                __nv_bfloat16 h1 = __float2bfloat16(v1);
                __nv_bfloat16 l0 = __float2bfloat16(v0 - __bfloat162float(h0));
                __nv_bfloat16 l1 = __float2bfloat16(v1 - __bfloat162float(h1));
                *(uint32_t*)(aoh + (size_t)q * DM + col) = pack_bf2(h0, h1);
                *(uint32_t*)(aol + (size_t)q * DM + col) = pack_bf2(l0, l1);
            }
        }
}

// ---------------------------------------------------------------------------
extern "C" void kernel_launch(void* const* d_in, const int* in_sizes, int n_in,
                              void* d_out, int out_size)
{
    const float* x  = (const float*)d_in[0];
    const float* Wq = (const float*)d_in[1];
    const float* Wk = (const float*)d_in[2];
    const float* Wv = (const float*)d_in[3];
    const float* Wo = (const float*)d_in[4];

    __nv_bfloat16 *xh, *xl, *wh, *wl, *qhp, *qlp, *khp, *klp, *vhp, *vlp, *aoh, *aol;
    cudaGetSymbolAddress((void**)&xh,  g_xh);
    cudaGetSymbolAddress((void**)&xl,  g_xl);
    cudaGetSymbolAddress((void**)&wh,  g_wh);
    cudaGetSymbolAddress((void**)&wl,  g_wl);
    cudaGetSymbolAddress((void**)&qhp, g_qh);
    cudaGetSymbolAddress((void**)&qlp, g_ql);
    cudaGetSymbolAddress((void**)&khp, g_kh);
    cudaGetSymbolAddress((void**)&klp, g_kl);
    cudaGetSymbolAddress((void**)&vhp, g_vh);
    cudaGetSymbolAddress((void**)&vlp, g_vl);
    cudaGetSymbolAddress((void**)&aoh, g_aoh);
    cudaGetSymbolAddress((void**)&aol, g_aol);

    const int nx2 = SEQ * DM / 2;
    const int nw2 = DM * DM / 2;
    split_bf16<<<(nx2 + 255) / 256, 256>>>(x, xh, xl, nx2);
    split4_bf16<<<dim3((nw2 + 255) / 256, 4), 256>>>(Wq, Wk, Wv, Wo, wh, wl, nw2);

    const int gsm = 2 * 4 * 10240;   // 81,920 B
    cudaFuncSetAttribute(gemm_mma, cudaFuncAttributeMaxDynamicSharedMemorySize, gsm);
    cudaFuncSetAttribute(flash_tc, cudaFuncAttributeMaxDynamicSharedMemorySize, A_TOT);

    // fused Q/K/V projections
    gemm_mma<<<dim3(DM / 128, SEQ / 128, 3), 256, gsm>>>(
        xh, xl, wh, wl, nullptr, qhp, qlp, khp, klp, vhp, vlp, 1);

    flash_tc<<<dim3(SEQ / 128, NH), 256, A_TOT>>>(qhp, qlp, khp, klp, vhp, vlp, aoh, aol);

    // Wo projection
    gemm_mma<<<dim3(DM / 128, SEQ / 128, 1), 256, gsm>>>(
        aoh, aol, wh, wl, (float*)d_out,
        nullptr, nullptr, nullptr, nullptr, nullptr, nullptr, 0);
}

// round 7
// speedup vs baseline: 3.1429x; 1.0788x over previous
#include <cuda_runtime.h>
#include <cuda_bf16.h>
#include <math.h>
#include <stdint.h>

#define SEQ 4096
#define DM  1024
#define NH  16
#define DK  64

// ---------------------------------------------------------------------------
// scratch (no allocs allowed) — all bf16 hi/lo pairs
// ---------------------------------------------------------------------------
__device__ __nv_bfloat16 g_xh [SEQ * DM];
__device__ __nv_bfloat16 g_xl [SEQ * DM];
__device__ __nv_bfloat16 g_wh [4][DM * DM];
__device__ __nv_bfloat16 g_wl [4][DM * DM];
__device__ __nv_bfloat16 g_qh [NH * SEQ * DK];
__device__ __nv_bfloat16 g_ql [NH * SEQ * DK];
__device__ __nv_bfloat16 g_kh [NH * SEQ * DK];
__device__ __nv_bfloat16 g_kl [NH * SEQ * DK];
__device__ __nv_bfloat16 g_vh [NH * SEQ * DK];
__device__ __nv_bfloat16 g_vl [NH * SEQ * DK];
__device__ __nv_bfloat16 g_aoh[SEQ * DM];
__device__ __nv_bfloat16 g_aol[SEQ * DM];

// ---------------------------------------------------------------------------
// helpers
// ---------------------------------------------------------------------------
static __device__ __forceinline__ uint32_t s2u(const void* p) {
    uint32_t a;
    asm("{ .reg .u64 t; cvta.to.shared.u64 t, %1; cvt.u32.u64 %0, t; }"
        : "=r"(a) : "l"(p));
    return a;
}
static __device__ __forceinline__ void ldsm4(uint32_t* r, uint32_t addr) {
    asm volatile("ldmatrix.sync.aligned.m8n8.x4.shared.b16 {%0,%1,%2,%3}, [%4];"
                 : "=r"(r[0]), "=r"(r[1]), "=r"(r[2]), "=r"(r[3]) : "r"(addr));
}
static __device__ __forceinline__ void ldsm4t(uint32_t* r, uint32_t addr) {
    asm volatile("ldmatrix.sync.aligned.m8n8.x4.trans.shared.b16 {%0,%1,%2,%3}, [%4];"
                 : "=r"(r[0]), "=r"(r[1]), "=r"(r[2]), "=r"(r[3]) : "r"(addr));
}
static __device__ __forceinline__ void mma16816(float* d, const uint32_t* a,
                                                uint32_t b0, uint32_t b1) {
    asm volatile(
        "mma.sync.aligned.m16n8k16.row.col.f32.bf16.bf16.f32 "
        "{%0,%1,%2,%3},{%4,%5,%6,%7},{%8,%9},{%0,%1,%2,%3};"
        : "+f"(d[0]), "+f"(d[1]), "+f"(d[2]), "+f"(d[3])
        : "r"(a[0]), "r"(a[1]), "r"(a[2]), "r"(a[3]), "r"(b0), "r"(b1));
}
static __device__ __forceinline__ void cp16(uint32_t s, const void* g) {
    asm volatile("cp.async.cg.shared.global [%0], [%1], 16;" :: "r"(s), "l"(g));
}
#define CP_COMMIT asm volatile("cp.async.commit_group;")
#define CP_WAIT0  asm volatile("cp.async.wait_group 0;")
#define CP_WAIT1  asm volatile("cp.async.wait_group 1;")

static __device__ __forceinline__ uint32_t pack_bf2(__nv_bfloat16 a, __nv_bfloat16 b) {
    return (uint32_t)__bfloat16_as_ushort(a) | ((uint32_t)__bfloat16_as_ushort(b) << 16);
}
// split a fp32 pair into packed bf16 hi and lo words
static __device__ __forceinline__ void split2(float v0, float v1,
                                              uint32_t& hi, uint32_t& lo) {
    __nv_bfloat16 h0 = __float2bfloat16(v0);
    __nv_bfloat16 h1 = __float2bfloat16(v1);
    __nv_bfloat16 l0 = __float2bfloat16(v0 - __bfloat162float(h0));
    __nv_bfloat16 l1 = __float2bfloat16(v1 - __bfloat162float(h1));
    hi = pack_bf2(h0, h1);
    lo = pack_bf2(l0, l1);
}

// ---------------------------------------------------------------------------
// split fp32 -> bf16 (hi, lo): x (1 launch) and the 4 weights (1 launch)
// ---------------------------------------------------------------------------
__global__ void __launch_bounds__(256)
split_bf16(const float* __restrict__ src, __nv_bfloat16* __restrict__ hi,
           __nv_bfloat16* __restrict__ lo, int n2)
{
    int i = blockIdx.x * 256 + threadIdx.x;
    if (i >= n2) return;
    float2 v = ((const float2*)src)[i];
    uint32_t h, l;
    split2(v.x, v.y, h, l);
    ((uint32_t*)hi)[i] = h;
    ((uint32_t*)lo)[i] = l;
}

__global__ void __launch_bounds__(256)
split4_bf16(const float* __restrict__ s0, const float* __restrict__ s1,
            const float* __restrict__ s2, const float* __restrict__ s3,
            __nv_bfloat16* __restrict__ hi, __nv_bfloat16* __restrict__ lo, int n2)
{
    int i = blockIdx.x * 256 + threadIdx.x;
    if (i >= n2) return;
    const int y = blockIdx.y;
    const float* s = (y == 0) ? s0 : (y == 1) ? s1 : (y == 2) ? s2 : s3;
    float2 v = ((const float2*)s)[i];
    uint32_t h, l;
    split2(v.x, v.y, h, l);
    const size_t base = (size_t)y * (DM * DM / 2);
    ((uint32_t*)hi)[base + i] = h;
    ((uint32_t*)lo)[base + i] = l;
}

// ---------------------------------------------------------------------------
// mma.sync bf16 split-3 GEMM (unchanged from R6)
// ---------------------------------------------------------------------------
__global__ void __launch_bounds__(256)
gemm_mma(const __nv_bfloat16* __restrict__ Ah_g, const __nv_bfloat16* __restrict__ Al_g,
         const __nv_bfloat16* __restrict__ WhAll, const __nv_bfloat16* __restrict__ WlAll,
         float* __restrict__ C,
         __nv_bfloat16* __restrict__ C0h, __nv_bfloat16* __restrict__ C0l,
         __nv_bfloat16* __restrict__ C1h, __nv_bfloat16* __restrict__ C1l,
         __nv_bfloat16* __restrict__ C2h, __nv_bfloat16* __restrict__ C2l,
         int qkv)
{
    constexpr int K = DM;
    constexpr int TILE  = 10240;   // 128 rows x 40 bf16 (pitch 80B)
    constexpr int STAGE = 4 * TILE;
    extern __shared__ __align__(128) char smg[];
    const uint32_t sbase = s2u(smg);

    const int z   = blockIdx.z;
    const int mode = qkv ? ((z == 2) ? 1 : 2) : 0;
    const size_t wsel = qkv ? (size_t)z * DM * DM : (size_t)3 * DM * DM;
    const __nv_bfloat16* Bh_g = WhAll + wsel;
    const __nv_bfloat16* Bl_g = WlAll + wsel;
    __nv_bfloat16* Ch = (z == 0) ? C0h : (z == 1) ? C1h : C2h;
    __nv_bfloat16* Cl = (z == 0) ? C0l : (z == 1) ? C1l : C2l;

    const int bm  = blockIdx.y * 128;
    const int bn  = blockIdx.x * 128;
    const int tid = threadIdx.x;
    const int lane = tid & 31;
    const int wid  = tid >> 5;
    const int wm = (wid >> 2) * 64;
    const int wn = (wid & 3) * 32;

    const __nv_bfloat16* srcs[4] = {
        Ah_g + (size_t)bm * K, Al_g + (size_t)bm * K,
        Bh_g + (size_t)bn * K, Bl_g + (size_t)bn * K };

    auto fill = [&](int s, int kc) {
#pragma unroll
        for (int t = 0; t < 4; ++t) {
#pragma unroll
            for (int i = 0; i < 2; ++i) {
                const int idx = i * 256 + tid;
                const int r = idx >> 2;
                const int c = idx & 3;
                cp16(sbase + s * STAGE + t * TILE + r * 80 + c * 16,
                     srcs[t] + (size_t)r * K + kc * 32 + c * 8);
            }
        }
        CP_COMMIT;
    };

    float acc[4][4][4] = {};

    fill(0, 0);
    for (int kc = 0; kc < K / 32; ++kc) {
        CP_WAIT0;
        __syncthreads();
        if (kc + 1 < K / 32) fill((kc + 1) & 1, kc + 1);

        const uint32_t aB = sbase + (kc & 1) * STAGE;
        const uint32_t bB = aB + 2 * TILE;
#pragma unroll
        for (int ks = 0; ks < 2; ++ks) {
            uint32_t ah[4][4], al[4][4], bh[2][4], bl[2][4];
#pragma unroll
            for (int mt = 0; mt < 4; ++mt) {
                const uint32_t ad = aB +
                    ((wm + mt * 16 + (lane & 15)) * 40 + ks * 16 + (lane >> 4) * 8) * 2;
                ldsm4(ah[mt], ad);
                ldsm4(al[mt], ad + TILE);
            }
#pragma unroll
            for (int np = 0; np < 2; ++np) {
                const uint32_t ad = bB +
                    ((wn + np * 16 + (lane & 15)) * 40 + ks * 16 + (lane >> 4) * 8) * 2;
                ldsm4(bh[np], ad);
                ldsm4(bl[np], ad + TILE);
            }
#pragma unroll
            for (int mt = 0; mt < 4; ++mt)
#pragma unroll
                for (int nt = 0; nt < 4; ++nt) {
                    const int np = nt >> 1, hf = nt & 1;
                    mma16816(acc[mt][nt], ah[mt], bh[np][hf], bh[np][hf + 2]);
                    mma16816(acc[mt][nt], ah[mt], bl[np][hf], bl[np][hf + 2]);
                    mma16816(acc[mt][nt], al[mt], bh[np][hf], bh[np][hf + 2]);
                }
        }
        __syncthreads();
    }

#pragma unroll
    for (int mt = 0; mt < 4; ++mt)
#pragma unroll
        for (int ri = 0; ri < 2; ++ri) {
            const int m = bm + wm + mt * 16 + ri * 8 + (lane >> 2);
#pragma unroll
            for (int nt = 0; nt < 4; ++nt) {
                const int n = bn + wn + nt * 8 + 2 * (lane & 3);
                float v0 = acc[mt][nt][ri * 2 + 0];
                float v1 = acc[mt][nt][ri * 2 + 1];
                if (mode == 0) {
                    *(float2*)(C + (size_t)m * DM + n) = make_float2(v0, v1);
                } else {
                    if (mode == 2) {
                        const int d = n & 63;   // even
                        const float inv = powf(10000.f, -(float)d / 64.f);
                        float sn, cs;
                        sincosf((float)m * inv, &sn, &cs);
                        const float a = v0, b = v1;
                        v0 = a * cs - b * sn;
                        v1 = b * cs + a * sn;
                    }
                    const int hh = n >> 6;
                    const int d0 = n & 63;
                    const size_t off = ((size_t)hh * SEQ + m) * DK + d0;
                    uint32_t h, l;
                    split2(v0, v1, h, l);
                    *(uint32_t*)(Ch + off) = h;
                    *(uint32_t*)(Cl + off) = l;
                }
            }
        }
}

// ---------------------------------------------------------------------------
// flash attention v2 (FA2-style register pipeline), causal, split-3 bf16 mma.
// 8 warps; warp w owns q-rows [w*16, w*16+16) of the 128-row tile and ALL
// 128 token columns / all 64 dk columns. Softmax is warp-local. P stays in
// registers (accumulator->A-fragment identity). Q fragments hoisted.
// K and V double-buffered in smem (pitch 72 bf16 = 144B); 2 syncs per iter.
// ---------------------------------------------------------------------------
#define F_K0  0        // hi at +0, lo at +18432
#define F_K1  36864
#define F_V0  73728
#define F_V1  110592
#define F_Q   147456
#define F_TOT 184320

__global__ void __launch_bounds__(256)
flash_tc(const __nv_bfloat16* __restrict__ qh, const __nv_bfloat16* __restrict__ ql,
         const __nv_bfloat16* __restrict__ kh, const __nv_bfloat16* __restrict__ kl,
         const __nv_bfloat16* __restrict__ vh, const __nv_bfloat16* __restrict__ vl,
         __nv_bfloat16* __restrict__ aoh, __nv_bfloat16* __restrict__ aol)
{
    extern __shared__ __align__(128) char sma[];
    const uint32_t sbase = s2u(sma);

    const int h    = blockIdx.y;
    const int qb   = gridDim.x - 1 - blockIdx.x;   // heavy tiles first
    const int tid  = threadIdx.x;
    const int lane = tid & 31;
    const int wid  = tid >> 5;
    const int wm   = wid * 16;          // this warp's q-row block
    const int g    = lane >> 2;         // row-in-8 group
    const int tq   = lane & 3;          // quad lane (column pair)

    const size_t hb = (size_t)h * SEQ * DK;

    // ---- prologue: Q (group), K0+V0 (group) ----
    {
        const __nv_bfloat16* qgh = qh + hb + (size_t)qb * 128 * DK;
        const __nv_bfloat16* qgl = ql + hb + (size_t)qb * 128 * DK;
#pragma unroll
        for (int i = 0; i < 4; ++i) {
            const int idx = i * 256 + tid;
            const int r = idx >> 3;
            const int c = idx & 7;
            cp16(sbase + F_Q + r * 144 + c * 16, qgh + r * 64 + c * 8);
            cp16(sbase + F_Q + 18432 + r * 144 + c * 16, qgl + r * 64 + c * 8);
        }
        CP_COMMIT;
        const __nv_bfloat16* kgh = kh + hb;
        const __nv_bfloat16* kgl = kl + hb;
        const __nv_bfloat16* vgh = vh + hb;
        const __nv_bfloat16* vgl = vl + hb;
#pragma unroll
        for (int i = 0; i < 4; ++i) {
            const int idx = i * 256 + tid;
            const int r = idx >> 3;
            const int c = idx & 7;
            cp16(sbase + F_K0 + r * 144 + c * 16, kgh + r * 64 + c * 8);
            cp16(sbase + F_K0 + 18432 + r * 144 + c * 16, kgl + r * 64 + c * 8);
            cp16(sbase + F_V0 + r * 144 + c * 16, vgh + r * 64 + c * 8);
            cp16(sbase + F_V0 + 18432 + r * 144 + c * 16, vgl + r * 64 + c * 8);
        }
        CP_COMMIT;
    }
    CP_WAIT1;            // Q resident (K0/V0 may still fly)
    __syncthreads();

    // ---- Q fragments (held in registers for the whole kernel) ----
    uint32_t qfh[4][4], qfl[4][4];
#pragma unroll
    for (int d16 = 0; d16 < 4; ++d16) {
        const uint32_t ad = sbase + F_Q +
            ((wm + (lane & 15)) * 72 + d16 * 16 + (lane >> 4) * 8) * 2;
        ldsm4(qfh[d16], ad);
        ldsm4(qfl[d16], ad + 18432);
    }

    float oacc[8][4] = {};
    float mrow[2] = { -1e30f, -1e30f };
    float lrow[2] = { 0.f, 0.f };

    for (int kb = 0; kb <= qb; ++kb) {
        __syncthreads();   // everyone done reading buf[(kb+1)&1] from iter kb-1

        // prefetch K,V (kb+1) into alt buffers
        if (kb < qb) {
            const __nv_bfloat16* kgh = kh + hb + (size_t)(kb + 1) * 128 * DK;
            const __nv_bfloat16* kgl = kl + hb + (size_t)(kb + 1) * 128 * DK;
            const __nv_bfloat16* vgh = vh + hb + (size_t)(kb + 1) * 128 * DK;
            const __nv_bfloat16* vgl = vl + hb + (size_t)(kb + 1) * 128 * DK;
            const uint32_t kB = sbase + (((kb + 1) & 1) ? F_K1 : F_K0);
            const uint32_t vB = sbase + (((kb + 1) & 1) ? F_V1 : F_V0);
#pragma unroll
            for (int i = 0; i < 4; ++i) {
                const int idx = i * 256 + tid;
                const int r = idx >> 3;
                const int c = idx & 7;
                cp16(kB + r * 144 + c * 16, kgh + r * 64 + c * 8);
                cp16(kB + 18432 + r * 144 + c * 16, kgl + r * 64 + c * 8);
                cp16(vB + r * 144 + c * 16, vgh + r * 64 + c * 8);
                cp16(vB + 18432 + r * 144 + c * 16, vgl + r * 64 + c * 8);
            }
        }
        CP_COMMIT;
        CP_WAIT1;          // K(kb), V(kb) complete
        __syncthreads();   // and visible to all warps

        const uint32_t kBuf = sbase + ((kb & 1) ? F_K1 : F_K0);
        const uint32_t vBuf = sbase + ((kb & 1) ? F_V1 : F_V0);

        // ---- S = Q K^T (3-term): 16 n8-tiles per warp ----
        float sacc[16][4] = {};
#pragma unroll
        for (int d16 = 0; d16 < 4; ++d16) {
#pragma unroll
            for (int ng = 0; ng < 8; ++ng) {
                uint32_t bh[4], bl[4];
                const uint32_t ad = kBuf +
                    ((ng * 16 + (lane & 15)) * 72 + d16 * 16 + (lane >> 4) * 8) * 2;
                ldsm4(bh, ad);
                ldsm4(bl, ad + 18432);
                mma16816(sacc[2 * ng],     qfh[d16], bh[0], bh[2]);
                mma16816(sacc[2 * ng],     qfh[d16], bl[0], bl[2]);
                mma16816(sacc[2 * ng],     qfl[d16], bh[0], bh[2]);
                mma16816(sacc[2 * ng + 1], qfh[d16], bh[1], bh[3]);
                mma16816(sacc[2 * ng + 1], qfh[d16], bl[1], bl[3]);
                mma16816(sacc[2 * ng + 1], qfl[d16], bh[1], bh[3]);
            }
        }

        // ---- warp-local online softmax (rows wm+g and wm+g+8) ----
        const bool diag = (kb == qb);
        float corr[2];
#pragma unroll
        for (int hf = 0; hf < 2; ++hf) {
            const int rloc = wm + g + hf * 8;
            float vmax = -1e30f;
#pragma unroll
            for (int j = 0; j < 16; ++j)
#pragma unroll
                for (int ci = 0; ci < 2; ++ci) {
                    float v = sacc[j][hf * 2 + ci] * 0.125f;
                    if (diag && (8 * j + 2 * tq + ci) > rloc) v = -1e30f;
                    sacc[j][hf * 2 + ci] = v;
                    vmax = fmaxf(vmax, v);
                }
            vmax = fmaxf(vmax, __shfl_xor_sync(0xffffffffu, vmax, 1));
            vmax = fmaxf(vmax, __shfl_xor_sync(0xffffffffu, vmax, 2));
            const float mnew = fmaxf(mrow[hf], vmax);
            corr[hf] = __expf(mrow[hf] - mnew);
            mrow[hf] = mnew;
            float rs = 0.f;
#pragma unroll
            for (int j = 0; j < 16; ++j)
#pragma unroll
                for (int ci = 0; ci < 2; ++ci) {
                    const float p = __expf(sacc[j][hf * 2 + ci] - mnew);
                    sacc[j][hf * 2 + ci] = p;
                    rs += p;
                }
            rs += __shfl_xor_sync(0xffffffffu, rs, 1);
            rs += __shfl_xor_sync(0xffffffffu, rs, 2);
            lrow[hf] = lrow[hf] * corr[hf] + rs;
#pragma unroll
            for (int j = 0; j < 8; ++j) {
                oacc[j][hf * 2 + 0] *= corr[hf];
                oacc[j][hf * 2 + 1] *= corr[hf];
            }
        }

        // ---- O += P V (3-term); P A-frags built in registers ----
#pragma unroll
        for (int kt = 0; kt < 8; ++kt) {
            uint32_t ah[4], al[4];
            split2(sacc[2 * kt][0],     sacc[2 * kt][1],     ah[0], al[0]);
            split2(sacc[2 * kt][2],     sacc[2 * kt][3],     ah[1], al[1]);
            split2(sacc[2 * kt + 1][0], sacc[2 * kt + 1][1], ah[2], al[2]);
            split2(sacc[2 * kt + 1][2], sacc[2 * kt + 1][3], ah[3], al[3]);
            const int t_loc = kt * 16 + (lane & 7) + ((lane >> 3) & 1) * 8;
#pragma unroll
            for (int ng = 0; ng < 4; ++ng) {
                uint32_t bh[4], bl[4];
                const int d_loc = ng * 16 + ((lane >> 4) & 1) * 8;
                const uint32_t ad = vBuf + (uint32_t)(t_loc * 72 + d_loc) * 2;
                ldsm4t(bh, ad);
                ldsm4t(bl, ad + 18432);
                mma16816(oacc[2 * ng],     ah, bh[0], bh[1]);
                mma16816(oacc[2 * ng],     ah, bl[0], bl[1]);
                mma16816(oacc[2 * ng],     al, bh[0], bh[1]);
                mma16816(oacc[2 * ng + 1], ah, bh[2], bh[3]);
                mma16816(oacc[2 * ng + 1], ah, bl[2], bl[3]);
                mma16816(oacc[2 * ng + 1], al, bh[2], bh[3]);
            }
        }
    }

    // ---- epilogue: normalize, split hi/lo, store [s][dm] ----
#pragma unroll
    for (int hf = 0; hf < 2; ++hf) {
        const float inv = 1.f / lrow[hf];
        const int q = qb * 128 + wm + g + hf * 8;
#pragma unroll
        for (int j = 0; j < 8; ++j) {
            const float v0 = oacc[j][hf * 2 + 0] * inv;
            const float v1 = oacc[j][hf * 2 + 1] * inv;
            const int col = h * 64 + 8 * j + 2 * tq;
            uint32_t hw, lw;
            split2(v0, v1, hw, lw);
            *(uint32_t*)(aoh + (size_t)q * DM + col) = hw;
            *(uint32_t*)(aol + (size_t)q * DM + col) = lw;
        }
    }
}

// ---------------------------------------------------------------------------
extern "C" void kernel_launch(void* const* d_in, const int* in_sizes, int n_in,
                              void* d_out, int out_size)
{
    const float* x  = (const float*)d_in[0];
    const float* Wq = (const float*)d_in[1];
    const float* Wk = (const float*)d_in[2];
    const float* Wv = (const float*)d_in[3];
    const float* Wo = (const float*)d_in[4];

    __nv_bfloat16 *xh, *xl, *wh, *wl, *qhp, *qlp, *khp, *klp, *vhp, *vlp, *aoh, *aol;
    cudaGetSymbolAddress((void**)&xh,  g_xh);
    cudaGetSymbolAddress((void**)&xl,  g_xl);
    cudaGetSymbolAddress((void**)&wh,  g_wh);
    cudaGetSymbolAddress((void**)&wl,  g_wl);
    cudaGetSymbolAddress((void**)&qhp, g_qh);
    cudaGetSymbolAddress((void**)&qlp, g_ql);
    cudaGetSymbolAddress((void**)&khp, g_kh);
    cudaGetSymbolAddress((void**)&klp, g_kl);
    cudaGetSymbolAddress((void**)&vhp, g_vh);
    cudaGetSymbolAddress((void**)&vlp, g_vl);
    cudaGetSymbolAddress((void**)&aoh, g_aoh);
    cudaGetSymbolAddress((void**)&aol, g_aol);

    const int nx2 = SEQ * DM / 2;
    const int nw2 = DM * DM / 2;
    split_bf16<<<(nx2 + 255) / 256, 256>>>(x, xh, xl, nx2);
    split4_bf16<<<dim3((nw2 + 255) / 256, 4), 256>>>(Wq, Wk, Wv, Wo, wh, wl, nw2);

    const int gsm = 2 * 4 * 10240;   // 81,920 B
    cudaFuncSetAttribute(gemm_mma, cudaFuncAttributeMaxDynamicSharedMemorySize, gsm);
    cudaFuncSetAttribute(flash_tc, cudaFuncAttributeMaxDynamicSharedMemorySize, F_TOT);

    // fused Q/K/V projections
    gemm_mma<<<dim3(DM / 128, SEQ / 128, 3), 256, gsm>>>(
        xh, xl, wh, wl, nullptr, qhp, qlp, khp, klp, vhp, vlp, 1);

    flash_tc<<<dim3(SEQ / 128, NH), 256, F_TOT>>>(qhp, qlp, khp, klp, vhp, vlp, aoh, aol);

    // Wo projection
    gemm_mma<<<dim3(DM / 128, SEQ / 128, 1), 256, gsm>>>(
        aoh, aol, wh, wl, (float*)d_out,
        nullptr, nullptr, nullptr, nullptr, nullptr, nullptr, 0);
}

// round 8
// speedup vs baseline: 3.1524x; 1.0030x over previous
#include <cuda_runtime.h>
#include <cuda_bf16.h>
#include <math.h>
#include <stdint.h>

#define SEQ 4096
#define DM  1024
#define NH  16
#define DK  64

// ---------------------------------------------------------------------------
// scratch (no allocs allowed) — all bf16 hi/lo pairs
// ---------------------------------------------------------------------------
__device__ __nv_bfloat16 g_xh [SEQ * DM];
__device__ __nv_bfloat16 g_xl [SEQ * DM];
__device__ __nv_bfloat16 g_wh [4][DM * DM];
__device__ __nv_bfloat16 g_wl [4][DM * DM];
__device__ __nv_bfloat16 g_qh [NH * SEQ * DK];
__device__ __nv_bfloat16 g_ql [NH * SEQ * DK];
__device__ __nv_bfloat16 g_kh [NH * SEQ * DK];
__device__ __nv_bfloat16 g_kl [NH * SEQ * DK];
__device__ __nv_bfloat16 g_vh [NH * SEQ * DK];
__device__ __nv_bfloat16 g_vl [NH * SEQ * DK];
__device__ __nv_bfloat16 g_aoh[SEQ * DM];
__device__ __nv_bfloat16 g_aol[SEQ * DM];

// ---------------------------------------------------------------------------
// helpers
// ---------------------------------------------------------------------------
static __device__ __forceinline__ uint32_t s2u(const void* p) {
    uint32_t a;
    asm("{ .reg .u64 t; cvta.to.shared.u64 t, %1; cvt.u32.u64 %0, t; }"
        : "=r"(a) : "l"(p));
    return a;
}
static __device__ __forceinline__ void ldsm4(uint32_t* r, uint32_t addr) {
    asm volatile("ldmatrix.sync.aligned.m8n8.x4.shared.b16 {%0,%1,%2,%3}, [%4];"
                 : "=r"(r[0]), "=r"(r[1]), "=r"(r[2]), "=r"(r[3]) : "r"(addr));
}
static __device__ __forceinline__ void ldsm4t(uint32_t* r, uint32_t addr) {
    asm volatile("ldmatrix.sync.aligned.m8n8.x4.trans.shared.b16 {%0,%1,%2,%3}, [%4];"
                 : "=r"(r[0]), "=r"(r[1]), "=r"(r[2]), "=r"(r[3]) : "r"(addr));
}
static __device__ __forceinline__ void mma16816(float* d, const uint32_t* a,
                                                uint32_t b0, uint32_t b1) {
    asm volatile(
        "mma.sync.aligned.m16n8k16.row.col.f32.bf16.bf16.f32 "
        "{%0,%1,%2,%3},{%4,%5,%6,%7},{%8,%9},{%0,%1,%2,%3};"
        : "+f"(d[0]), "+f"(d[1]), "+f"(d[2]), "+f"(d[3])
        : "r"(a[0]), "r"(a[1]), "r"(a[2]), "r"(a[3]), "r"(b0), "r"(b1));
}
static __device__ __forceinline__ void cp16(uint32_t s, const void* g) {
    asm volatile("cp.async.cg.shared.global [%0], [%1], 16;" :: "r"(s), "l"(g));
}
#define CP_COMMIT asm volatile("cp.async.commit_group;")
#define CP_WAIT0  asm volatile("cp.async.wait_group 0;")
#define CP_WAIT1  asm volatile("cp.async.wait_group 1;")

static __device__ __forceinline__ uint32_t pack_bf2(__nv_bfloat16 a, __nv_bfloat16 b) {
    return (uint32_t)__bfloat16_as_ushort(a) | ((uint32_t)__bfloat16_as_ushort(b) << 16);
}
static __device__ __forceinline__ void split2(float v0, float v1,
                                              uint32_t& hi, uint32_t& lo) {
    __nv_bfloat16 h0 = __float2bfloat16(v0);
    __nv_bfloat16 h1 = __float2bfloat16(v1);
    __nv_bfloat16 l0 = __float2bfloat16(v0 - __bfloat162float(h0));
    __nv_bfloat16 l1 = __float2bfloat16(v1 - __bfloat162float(h1));
    hi = pack_bf2(h0, h1);
    lo = pack_bf2(l0, l1);
}

// ---------------------------------------------------------------------------
// split fp32 -> bf16 (hi, lo)
// ---------------------------------------------------------------------------
__global__ void __launch_bounds__(256)
split_bf16(const float* __restrict__ src, __nv_bfloat16* __restrict__ hi,
           __nv_bfloat16* __restrict__ lo, int n2)
{
    int i = blockIdx.x * 256 + threadIdx.x;
    if (i >= n2) return;
    float2 v = ((const float2*)src)[i];
    uint32_t h, l;
    split2(v.x, v.y, h, l);
    ((uint32_t*)hi)[i] = h;
    ((uint32_t*)lo)[i] = l;
}

__global__ void __launch_bounds__(256)
split4_bf16(const float* __restrict__ s0, const float* __restrict__ s1,
            const float* __restrict__ s2, const float* __restrict__ s3,
            __nv_bfloat16* __restrict__ hi, __nv_bfloat16* __restrict__ lo, int n2)
{
    int i = blockIdx.x * 256 + threadIdx.x;
    if (i >= n2) return;
    const int y = blockIdx.y;
    const float* s = (y == 0) ? s0 : (y == 1) ? s1 : (y == 2) ? s2 : s3;
    float2 v = ((const float2*)s)[i];
    uint32_t h, l;
    split2(v.x, v.y, h, l);
    const size_t base = (size_t)y * (DM * DM / 2);
    ((uint32_t*)hi)[base + i] = h;
    ((uint32_t*)lo)[base + i] = l;
}

// ---------------------------------------------------------------------------
// mma.sync bf16 split-3 GEMM. 128x128x32 tiles, cp.async double-buffered,
// 8 warps (2m x 4n). __launch_bounds__(256,2) => <=128 regs, 2 CTAs/SM.
// Q output (z==0) is pre-scaled by 1/8 (softmax scale folded in).
// ---------------------------------------------------------------------------
__global__ void __launch_bounds__(256, 2)
gemm_mma(const __nv_bfloat16* __restrict__ Ah_g, const __nv_bfloat16* __restrict__ Al_g,
         const __nv_bfloat16* __restrict__ WhAll, const __nv_bfloat16* __restrict__ WlAll,
         float* __restrict__ C,
         __nv_bfloat16* __restrict__ C0h, __nv_bfloat16* __restrict__ C0l,
         __nv_bfloat16* __restrict__ C1h, __nv_bfloat16* __restrict__ C1l,
         __nv_bfloat16* __restrict__ C2h, __nv_bfloat16* __restrict__ C2l,
         int qkv)
{
    constexpr int K = DM;
    constexpr int TILE  = 10240;   // 128 rows x 40 bf16 (pitch 80B)
    constexpr int STAGE = 4 * TILE;
    extern __shared__ __align__(128) char smg[];
    const uint32_t sbase = s2u(smg);

    const int z   = blockIdx.z;
    const int mode = qkv ? ((z == 2) ? 1 : 2) : 0;
    const float oscale = (qkv && z == 0) ? 0.125f : 1.0f;
    const size_t wsel = qkv ? (size_t)z * DM * DM : (size_t)3 * DM * DM;
    const __nv_bfloat16* Bh_g = WhAll + wsel;
    const __nv_bfloat16* Bl_g = WlAll + wsel;
    __nv_bfloat16* Ch = (z == 0) ? C0h : (z == 1) ? C1h : C2h;
    __nv_bfloat16* Cl = (z == 0) ? C0l : (z == 1) ? C1l : C2l;

    const int bm  = blockIdx.y * 128;
    const int bn  = blockIdx.x * 128;
    const int tid = threadIdx.x;
    const int lane = tid & 31;
    const int wid  = tid >> 5;
    const int wm = (wid >> 2) * 64;
    const int wn = (wid & 3) * 32;

    const __nv_bfloat16* srcs[4] = {
        Ah_g + (size_t)bm * K, Al_g + (size_t)bm * K,
        Bh_g + (size_t)bn * K, Bl_g + (size_t)bn * K };

    auto fill = [&](int s, int kc) {
#pragma unroll
        for (int t = 0; t < 4; ++t) {
#pragma unroll
            for (int i = 0; i < 2; ++i) {
                const int idx = i * 256 + tid;
                const int r = idx >> 2;
                const int c = idx & 3;
                cp16(sbase + s * STAGE + t * TILE + r * 80 + c * 16,
                     srcs[t] + (size_t)r * K + kc * 32 + c * 8);
            }
        }
        CP_COMMIT;
    };

    float acc[4][4][4] = {};

    fill(0, 0);
    for (int kc = 0; kc < K / 32; ++kc) {
        CP_WAIT0;
        __syncthreads();
        if (kc + 1 < K / 32) fill((kc + 1) & 1, kc + 1);

        const uint32_t aB = sbase + (kc & 1) * STAGE;
        const uint32_t bB = aB + 2 * TILE;
#pragma unroll
        for (int ks = 0; ks < 2; ++ks) {
            uint32_t ah[4][4], al[4][4];
#pragma unroll
            for (int mt = 0; mt < 4; ++mt) {
                const uint32_t ad = aB +
                    ((wm + mt * 16 + (lane & 15)) * 40 + ks * 16 + (lane >> 4) * 8) * 2;
                ldsm4(ah[mt], ad);
                ldsm4(al[mt], ad + TILE);
            }
#pragma unroll
            for (int np = 0; np < 2; ++np) {
                uint32_t bh[4], bl[4];
                const uint32_t ad = bB +
                    ((wn + np * 16 + (lane & 15)) * 40 + ks * 16 + (lane >> 4) * 8) * 2;
                ldsm4(bh, ad);
                ldsm4(bl, ad + TILE);
#pragma unroll
                for (int mt = 0; mt < 4; ++mt)
#pragma unroll
                    for (int hf = 0; hf < 2; ++hf) {
                        float* a4 = acc[mt][np * 2 + hf];
                        mma16816(a4, ah[mt], bh[hf], bh[hf + 2]);
                        mma16816(a4, ah[mt], bl[hf], bl[hf + 2]);
                        mma16816(a4, al[mt], bh[hf], bh[hf + 2]);
                    }
            }
        }
        __syncthreads();
    }

#pragma unroll
    for (int mt = 0; mt < 4; ++mt)
#pragma unroll
        for (int ri = 0; ri < 2; ++ri) {
            const int m = bm + wm + mt * 16 + ri * 8 + (lane >> 2);
#pragma unroll
            for (int nt = 0; nt < 4; ++nt) {
                const int n = bn + wn + nt * 8 + 2 * (lane & 3);
                float v0 = acc[mt][nt][ri * 2 + 0];
                float v1 = acc[mt][nt][ri * 2 + 1];
                if (mode == 0) {
                    *(float2*)(C + (size_t)m * DM + n) = make_float2(v0, v1);
                } else {
                    if (mode == 2) {
                        const int d = n & 63;   // even
                        const float inv = powf(10000.f, -(float)d / 64.f);
                        float sn, cs;
                        sincosf((float)m * inv, &sn, &cs);
                        const float a = v0, b = v1;
                        v0 = (a * cs - b * sn) * oscale;
                        v1 = (b * cs + a * sn) * oscale;
                    }
                    const int hh = n >> 6;
                    const int d0 = n & 63;
                    const size_t off = ((size_t)hh * SEQ + m) * DK + d0;
                    uint32_t h, l;
                    split2(v0, v1, h, l);
                    *(uint32_t*)(Ch + off) = h;
                    *(uint32_t*)(Cl + off) = l;
                }
            }
        }
}

// ---------------------------------------------------------------------------
// FA2-style flash attention, causal, split-3 bf16 mma.
// Br=128 (8 warps x 16 rows), Bc=64. K/V double-buffered (108 KB smem),
// __launch_bounds__(256,2) => 2 CTAs/SM for cross-CTA latency hiding.
// Q pre-scaled by 1/8 at projection. Softmax warp-local; P stays in regs.
// ---------------------------------------------------------------------------
#define F_K0  0        // 64x144B hi + lo(+9216)
#define F_K1  18432
#define F_V0  36864
#define F_V1  55296
#define F_Q   73728    // 128x144B hi + lo(+18432)
#define F_TOT 110592

__global__ void __launch_bounds__(256, 2)
flash_tc(const __nv_bfloat16* __restrict__ qh, const __nv_bfloat16* __restrict__ ql,
         const __nv_bfloat16* __restrict__ kh, const __nv_bfloat16* __restrict__ kl,
         const __nv_bfloat16* __restrict__ vh, const __nv_bfloat16* __restrict__ vl,
         __nv_bfloat16* __restrict__ aoh, __nv_bfloat16* __restrict__ aol)
{
    extern __shared__ __align__(128) char sma[];
    const uint32_t sbase = s2u(sma);

    const int h    = blockIdx.y;
    const int qb   = gridDim.x - 1 - blockIdx.x;   // heavy tiles first
    const int tid  = threadIdx.x;
    const int lane = tid & 31;
    const int wid  = tid >> 5;
    const int wm   = wid * 16;
    const int g    = lane >> 2;
    const int tq   = lane & 3;

    const size_t hb = (size_t)h * SEQ * DK;
    const int nkb = 2 * qb + 2;     // number of 64-token blocks

    // ---- prologue: Q (group), K0+V0 (group) ----
    {
        const __nv_bfloat16* qgh = qh + hb + (size_t)qb * 128 * DK;
        const __nv_bfloat16* qgl = ql + hb + (size_t)qb * 128 * DK;
#pragma unroll
        for (int i = 0; i < 4; ++i) {
            const int idx = i * 256 + tid;
            const int r = idx >> 3;
            const int c = idx & 7;
            cp16(sbase + F_Q + r * 144 + c * 16, qgh + r * 64 + c * 8);
            cp16(sbase + F_Q + 18432 + r * 144 + c * 16, qgl + r * 64 + c * 8);
        }
        CP_COMMIT;
        const __nv_bfloat16* kgh = kh + hb;
        const __nv_bfloat16* kgl = kl + hb;
        const __nv_bfloat16* vgh = vh + hb;
        const __nv_bfloat16* vgl = vl + hb;
#pragma unroll
        for (int i = 0; i < 2; ++i) {
            const int idx = i * 256 + tid;
            const int r = idx >> 3;        // 0..63
            const int c = idx & 7;
            cp16(sbase + F_K0 + r * 144 + c * 16, kgh + r * 64 + c * 8);
            cp16(sbase + F_K0 + 9216 + r * 144 + c * 16, kgl + r * 64 + c * 8);
            cp16(sbase + F_V0 + r * 144 + c * 16, vgh + r * 64 + c * 8);
            cp16(sbase + F_V0 + 9216 + r * 144 + c * 16, vgl + r * 64 + c * 8);
        }
        CP_COMMIT;
    }
    CP_WAIT1;
    __syncthreads();

    // ---- Q fragments (resident all kernel) ----
    uint32_t qfh[4][4], qfl[4][4];
#pragma unroll
    for (int d16 = 0; d16 < 4; ++d16) {
        const uint32_t ad = sbase + F_Q +
            ((wm + (lane & 15)) * 72 + d16 * 16 + (lane >> 4) * 8) * 2;
        ldsm4(qfh[d16], ad);
        ldsm4(qfl[d16], ad + 18432);
    }

    float oacc[8][4] = {};
    float mrow[2] = { -1e30f, -1e30f };
    float lrow[2] = { 0.f, 0.f };

    for (int kb = 0; kb < nkb; ++kb) {
        __syncthreads();

        // prefetch K,V (kb+1)
        if (kb + 1 < nkb) {
            const __nv_bfloat16* kgh = kh + hb + (size_t)(kb + 1) * 64 * DK;
            const __nv_bfloat16* kgl = kl + hb + (size_t)(kb + 1) * 64 * DK;
            const __nv_bfloat16* vgh = vh + hb + (size_t)(kb + 1) * 64 * DK;
            const __nv_bfloat16* vgl = vl + hb + (size_t)(kb + 1) * 64 * DK;
            const uint32_t kB = sbase + (((kb + 1) & 1) ? F_K1 : F_K0);
            const uint32_t vB = sbase + (((kb + 1) & 1) ? F_V1 : F_V0);
#pragma unroll
            for (int i = 0; i < 2; ++i) {
                const int idx = i * 256 + tid;
                const int r = idx >> 3;
                const int c = idx & 7;
                cp16(kB + r * 144 + c * 16, kgh + r * 64 + c * 8);
                cp16(kB + 9216 + r * 144 + c * 16, kgl + r * 64 + c * 8);
                cp16(vB + r * 144 + c * 16, vgh + r * 64 + c * 8);
                cp16(vB + 9216 + r * 144 + c * 16, vgl + r * 64 + c * 8);
            }
        }
        CP_COMMIT;
        CP_WAIT1;
        __syncthreads();

        const uint32_t kBuf = sbase + ((kb & 1) ? F_K1 : F_K0);
        const uint32_t vBuf = sbase + ((kb & 1) ? F_V1 : F_V0);

        // ---- S = Q K^T (3-term): 8 n8-tiles per warp ----
        float sacc[8][4] = {};
#pragma unroll
        for (int d16 = 0; d16 < 4; ++d16) {
#pragma unroll
            for (int ng = 0; ng < 4; ++ng) {
                uint32_t bh[4], bl[4];
                const uint32_t ad = kBuf +
                    ((ng * 16 + (lane & 15)) * 72 + d16 * 16 + (lane >> 4) * 8) * 2;
                ldsm4(bh, ad);
                ldsm4(bl, ad + 9216);
                mma16816(sacc[2 * ng],     qfh[d16], bh[0], bh[2]);
                mma16816(sacc[2 * ng],     qfh[d16], bl[0], bl[2]);
                mma16816(sacc[2 * ng],     qfl[d16], bh[0], bh[2]);
                mma16816(sacc[2 * ng + 1], qfh[d16], bh[1], bh[3]);
                mma16816(sacc[2 * ng + 1], qfh[d16], bl[1], bl[3]);
                mma16816(sacc[2 * ng + 1], qfl[d16], bh[1], bh[3]);
            }
        }

        // ---- warp-local online softmax (scale already folded into Q) ----
        const bool diag = (kb >= 2 * qb);
        const int moff = (kb - 2 * qb) * 64;    // valid when diag
        float corr[2];
#pragma unroll
        for (int hf = 0; hf < 2; ++hf) {
            const int rloc = wm + g + hf * 8;
            float vmax = -1e30f;
#pragma unroll
            for (int j = 0; j < 8; ++j)
#pragma unroll
                for (int ci = 0; ci < 2; ++ci) {
                    float v = sacc[j][hf * 2 + ci];
                    if (diag && (moff + 8 * j + 2 * tq + ci) > rloc) v = -1e30f;
                    sacc[j][hf * 2 + ci] = v;
                    vmax = fmaxf(vmax, v);
                }
            vmax = fmaxf(vmax, __shfl_xor_sync(0xffffffffu, vmax, 1));
            vmax = fmaxf(vmax, __shfl_xor_sync(0xffffffffu, vmax, 2));
            const float mnew = fmaxf(mrow[hf], vmax);
            corr[hf] = __expf(mrow[hf] - mnew);
            mrow[hf] = mnew;
            float rs = 0.f;
#pragma unroll
            for (int j = 0; j < 8; ++j)
#pragma unroll
                for (int ci = 0; ci < 2; ++ci) {
                    const float p = __expf(sacc[j][hf * 2 + ci] - mnew);
                    sacc[j][hf * 2 + ci] = p;
                    rs += p;
                }
            rs += __shfl_xor_sync(0xffffffffu, rs, 1);
            rs += __shfl_xor_sync(0xffffffffu, rs, 2);
            lrow[hf] = lrow[hf] * corr[hf] + rs;
#pragma unroll
            for (int j = 0; j < 8; ++j) {
                oacc[j][hf * 2 + 0] *= corr[hf];
                oacc[j][hf * 2 + 1] *= corr[hf];
            }
        }

        // ---- O += P V (3-term); P A-frags built in registers ----
#pragma unroll
        for (int kt = 0; kt < 4; ++kt) {
            uint32_t ah[4], al[4];
            split2(sacc[2 * kt][0],     sacc[2 * kt][1],     ah[0], al[0]);
            split2(sacc[2 * kt][2],     sacc[2 * kt][3],     ah[1], al[1]);
            split2(sacc[2 * kt + 1][0], sacc[2 * kt + 1][1], ah[2], al[2]);
            split2(sacc[2 * kt + 1][2], sacc[2 * kt + 1][3], ah[3], al[3]);
            const int t_loc = kt * 16 + (lane & 7) + ((lane >> 3) & 1) * 8;
#pragma unroll
            for (int ng = 0; ng < 4; ++ng) {
                uint32_t bh[4], bl[4];
                const int d_loc = ng * 16 + ((lane >> 4) & 1) * 8;
                const uint32_t ad = vBuf + (uint32_t)(t_loc * 72 + d_loc) * 2;
                ldsm4t(bh, ad);
                ldsm4t(bl, ad + 9216);
                mma16816(oacc[2 * ng],     ah, bh[0], bh[1]);
                mma16816(oacc[2 * ng],     ah, bl[0], bl[1]);
                mma16816(oacc[2 * ng],     al, bh[0], bh[1]);
                mma16816(oacc[2 * ng + 1], ah, bh[2], bh[3]);
                mma16816(oacc[2 * ng + 1], ah, bl[2], bl[3]);
                mma16816(oacc[2 * ng + 1], al, bh[2], bh[3]);
            }
        }
    }

    // ---- epilogue ----
#pragma unroll
    for (int hf = 0; hf < 2; ++hf) {
        const float inv = 1.f / lrow[hf];
        const int q = qb * 128 + wm + g + hf * 8;
#pragma unroll
        for (int j = 0; j < 8; ++j) {
            const float v0 = oacc[j][hf * 2 + 0] * inv;
            const float v1 = oacc[j][hf * 2 + 1] * inv;
            const int col = h * 64 + 8 * j + 2 * tq;
            uint32_t hw, lw;
            split2(v0, v1, hw, lw);
            *(uint32_t*)(aoh + (size_t)q * DM + col) = hw;
            *(uint32_t*)(aol + (size_t)q * DM + col) = lw;
        }
    }
}

// ---------------------------------------------------------------------------
extern "C" void kernel_launch(void* const* d_in, const int* in_sizes, int n_in,
                              void* d_out, int out_size)
{
    const float* x  = (const float*)d_in[0];
    const float* Wq = (const float*)d_in[1];
    const float* Wk = (const float*)d_in[2];
    const float* Wv = (const float*)d_in[3];
    const float* Wo = (const float*)d_in[4];

    __nv_bfloat16 *xh, *xl, *wh, *wl, *qhp, *qlp, *khp, *klp, *vhp, *vlp, *aoh, *aol;
    cudaGetSymbolAddress((void**)&xh,  g_xh);
    cudaGetSymbolAddress((void**)&xl,  g_xl);
    cudaGetSymbolAddress((void**)&wh,  g_wh);
    cudaGetSymbolAddress((void**)&wl,  g_wl);
    cudaGetSymbolAddress((void**)&qhp, g_qh);
    cudaGetSymbolAddress((void**)&qlp, g_ql);
    cudaGetSymbolAddress((void**)&khp, g_kh);
    cudaGetSymbolAddress((void**)&klp, g_kl);
    cudaGetSymbolAddress((void**)&vhp, g_vh);
    cudaGetSymbolAddress((void**)&vlp, g_vl);
    cudaGetSymbolAddress((void**)&aoh, g_aoh);
    cudaGetSymbolAddress((void**)&aol, g_aol);

    const int nx2 = SEQ * DM / 2;
    const int nw2 = DM * DM / 2;
    split_bf16<<<(nx2 + 255) / 256, 256>>>(x, xh, xl, nx2);
    split4_bf16<<<dim3((nw2 + 255) / 256, 4), 256>>>(Wq, Wk, Wv, Wo, wh, wl, nw2);

    const int gsm = 2 * 4 * 10240;   // 81,920 B
    cudaFuncSetAttribute(gemm_mma, cudaFuncAttributeMaxDynamicSharedMemorySize, gsm);
    cudaFuncSetAttribute(flash_tc, cudaFuncAttributeMaxDynamicSharedMemorySize, F_TOT);

    // fused Q/K/V projections (Q pre-scaled by 1/8)
    gemm_mma<<<dim3(DM / 128, SEQ / 128, 3), 256, gsm>>>(
        xh, xl, wh, wl, nullptr, qhp, qlp, khp, klp, vhp, vlp, 1);

    flash_tc<<<dim3(SEQ / 128, NH), 256, F_TOT>>>(qhp, qlp, khp, klp, vhp, vlp, aoh, aol);

    // Wo projection
    gemm_mma<<<dim3(DM / 128, SEQ / 128, 1), 256, gsm>>>(
        aoh, aol, wh, wl, (float*)d_out,
        nullptr, nullptr, nullptr, nullptr, nullptr, nullptr, 0);
}

// round 9
// speedup vs baseline: 3.5257x; 1.1184x over previous
#include <cuda_runtime.h>
#include <cuda_fp16.h>
#include <math.h>
#include <stdint.h>

#define SEQ 4096
#define DM  1024
#define NH  16
#define DK  64

// ---------------------------------------------------------------------------
// scratch (no allocs allowed) — fp16 hi/lo pairs (V consumed hi-only)
// ---------------------------------------------------------------------------
__device__ __half g_xh [SEQ * DM];
__device__ __half g_xl [SEQ * DM];
__device__ __half g_wh [4][DM * DM];
__device__ __half g_wl [4][DM * DM];
__device__ __half g_qh [NH * SEQ * DK];
__device__ __half g_ql [NH * SEQ * DK];
__device__ __half g_kh [NH * SEQ * DK];
__device__ __half g_kl [NH * SEQ * DK];
__device__ __half g_vh [NH * SEQ * DK];
__device__ __half g_aoh[SEQ * DM];
__device__ __half g_aol[SEQ * DM];

// ---------------------------------------------------------------------------
// helpers
// ---------------------------------------------------------------------------
static __device__ __forceinline__ uint32_t s2u(const void* p) {
    uint32_t a;
    asm("{ .reg .u64 t; cvta.to.shared.u64 t, %1; cvt.u32.u64 %0, t; }"
        : "=r"(a) : "l"(p));
    return a;
}
static __device__ __forceinline__ void ldsm4(uint32_t* r, uint32_t addr) {
    asm volatile("ldmatrix.sync.aligned.m8n8.x4.shared.b16 {%0,%1,%2,%3}, [%4];"
                 : "=r"(r[0]), "=r"(r[1]), "=r"(r[2]), "=r"(r[3]) : "r"(addr));
}
static __device__ __forceinline__ void ldsm4t(uint32_t* r, uint32_t addr) {
    asm volatile("ldmatrix.sync.aligned.m8n8.x4.trans.shared.b16 {%0,%1,%2,%3}, [%4];"
                 : "=r"(r[0]), "=r"(r[1]), "=r"(r[2]), "=r"(r[3]) : "r"(addr));
}
static __device__ __forceinline__ void mma16816(float* d, const uint32_t* a,
                                                uint32_t b0, uint32_t b1) {
    asm volatile(
        "mma.sync.aligned.m16n8k16.row.col.f32.f16.f16.f32 "
        "{%0,%1,%2,%3},{%4,%5,%6,%7},{%8,%9},{%0,%1,%2,%3};"
        : "+f"(d[0]), "+f"(d[1]), "+f"(d[2]), "+f"(d[3])
        : "r"(a[0]), "r"(a[1]), "r"(a[2]), "r"(a[3]), "r"(b0), "r"(b1));
}
static __device__ __forceinline__ void cp16(uint32_t s, const void* g) {
    asm volatile("cp.async.cg.shared.global [%0], [%1], 16;" :: "r"(s), "l"(g));
}
#define CP_COMMIT asm volatile("cp.async.commit_group;")
#define CP_WAIT0  asm volatile("cp.async.wait_group 0;")
#define CP_WAIT1  asm volatile("cp.async.wait_group 1;")

static __device__ __forceinline__ uint32_t pack_h2(__half a, __half b) {
    __half2 t = __halves2half2(a, b);
    return *reinterpret_cast<uint32_t*>(&t);
}
// split fp32 pair into packed fp16 hi and lo words
static __device__ __forceinline__ void split2(float v0, float v1,
                                              uint32_t& hi, uint32_t& lo) {
    __half h0 = __float2half_rn(v0);
    __half h1 = __float2half_rn(v1);
    __half l0 = __float2half_rn(v0 - __half2float(h0));
    __half l1 = __float2half_rn(v1 - __half2float(h1));
    hi = pack_h2(h0, h1);
    lo = pack_h2(l0, l1);
}

// ---------------------------------------------------------------------------
// split fp32 -> fp16 (hi, lo)
// ---------------------------------------------------------------------------
__global__ void __launch_bounds__(256)
split_bf16(const float* __restrict__ src, __half* __restrict__ hi,
           __half* __restrict__ lo, int n2)
{
    int i = blockIdx.x * 256 + threadIdx.x;
    if (i >= n2) return;
    float2 v = ((const float2*)src)[i];
    uint32_t h, l;
    split2(v.x, v.y, h, l);
    ((uint32_t*)hi)[i] = h;
    ((uint32_t*)lo)[i] = l;
}

__global__ void __launch_bounds__(256)
split4_bf16(const float* __restrict__ s0, const float* __restrict__ s1,
            const float* __restrict__ s2, const float* __restrict__ s3,
            __half* __restrict__ hi, __half* __restrict__ lo, int n2)
{
    int i = blockIdx.x * 256 + threadIdx.x;
    if (i >= n2) return;
    const int y = blockIdx.y;
    const float* s = (y == 0) ? s0 : (y == 1) ? s1 : (y == 2) ? s2 : s3;
    float2 v = ((const float2*)s)[i];
    uint32_t h, l;
    split2(v.x, v.y, h, l);
    const size_t base = (size_t)y * (DM * DM / 2);
    ((uint32_t*)hi)[base + i] = h;
    ((uint32_t*)lo)[base + i] = l;
}

// ---------------------------------------------------------------------------
// mma.sync fp16 split-3 GEMM. 128x128x32 tiles, cp.async double-buffered,
// 8 warps (2m x 4n), 2 CTAs/SM. Q output (z==0) pre-scaled by 0.125*log2(e)
// (softmax scale + exp2 conversion folded in).
// ---------------------------------------------------------------------------
__global__ void __launch_bounds__(256, 2)
gemm_mma(const __half* __restrict__ Ah_g, const __half* __restrict__ Al_g,
         const __half* __restrict__ WhAll, const __half* __restrict__ WlAll,
         float* __restrict__ C,
         __half* __restrict__ C0h, __half* __restrict__ C0l,
         __half* __restrict__ C1h, __half* __restrict__ C1l,
         __half* __restrict__ C2h, __half* __restrict__ C2l,
         int qkv)
{
    constexpr int K = DM;
    constexpr int TILE  = 10240;   // 128 rows x 40 fp16 (pitch 80B)
    constexpr int STAGE = 4 * TILE;
    extern __shared__ __align__(128) char smg[];
    const uint32_t sbase = s2u(smg);

    const int z   = blockIdx.z;
    const int mode = qkv ? ((z == 2) ? 1 : 2) : 0;
    const float oscale = (qkv && z == 0) ? 0.125f * 1.44269504f : 1.0f;
    const size_t wsel = qkv ? (size_t)z * DM * DM : (size_t)3 * DM * DM;
    const __half* Bh_g = WhAll + wsel;
    const __half* Bl_g = WlAll + wsel;
    __half* Ch = (z == 0) ? C0h : (z == 1) ? C1h : C2h;
    __half* Cl = (z == 0) ? C0l : (z == 1) ? C1l : C2l;

    const int bm  = blockIdx.y * 128;
    const int bn  = blockIdx.x * 128;
    const int tid = threadIdx.x;
    const int lane = tid & 31;
    const int wid  = tid >> 5;
    const int wm = (wid >> 2) * 64;
    const int wn = (wid & 3) * 32;

    const __half* srcs[4] = {
        Ah_g + (size_t)bm * K, Al_g + (size_t)bm * K,
        Bh_g + (size_t)bn * K, Bl_g + (size_t)bn * K };

    auto fill = [&](int s, int kc) {
#pragma unroll
        for (int t = 0; t < 4; ++t) {
#pragma unroll
            for (int i = 0; i < 2; ++i) {
                const int idx = i * 256 + tid;
                const int r = idx >> 2;
                const int c = idx & 3;
                cp16(sbase + s * STAGE + t * TILE + r * 80 + c * 16,
                     srcs[t] + (size_t)r * K + kc * 32 + c * 8);
            }
        }
        CP_COMMIT;
    };

    float acc[4][4][4] = {};

    fill(0, 0);
    for (int kc = 0; kc < K / 32; ++kc) {
        CP_WAIT0;
        __syncthreads();
        if (kc + 1 < K / 32) fill((kc + 1) & 1, kc + 1);

        const uint32_t aB = sbase + (kc & 1) * STAGE;
        const uint32_t bB = aB + 2 * TILE;
#pragma unroll
        for (int ks = 0; ks < 2; ++ks) {
            uint32_t ah[4][4], al[4][4];
#pragma unroll
            for (int mt = 0; mt < 4; ++mt) {
                const uint32_t ad = aB +
                    ((wm + mt * 16 + (lane & 15)) * 40 + ks * 16 + (lane >> 4) * 8) * 2;
                ldsm4(ah[mt], ad);
                ldsm4(al[mt], ad + TILE);
            }
#pragma unroll
            for (int np = 0; np < 2; ++np) {
                uint32_t bh[4], bl[4];
                const uint32_t ad = bB +
                    ((wn + np * 16 + (lane & 15)) * 40 + ks * 16 + (lane >> 4) * 8) * 2;
                ldsm4(bh, ad);
                ldsm4(bl, ad + TILE);
#pragma unroll
                for (int mt = 0; mt < 4; ++mt)
#pragma unroll
                    for (int hf = 0; hf < 2; ++hf) {
                        float* a4 = acc[mt][np * 2 + hf];
                        mma16816(a4, ah[mt], bh[hf], bh[hf + 2]);
                        mma16816(a4, ah[mt], bl[hf], bl[hf + 2]);
                        mma16816(a4, al[mt], bh[hf], bh[hf + 2]);
                    }
            }
        }
        __syncthreads();
    }

#pragma unroll
    for (int mt = 0; mt < 4; ++mt)
#pragma unroll
        for (int ri = 0; ri < 2; ++ri) {
            const int m = bm + wm + mt * 16 + ri * 8 + (lane >> 2);
#pragma unroll
            for (int nt = 0; nt < 4; ++nt) {
                const int n = bn + wn + nt * 8 + 2 * (lane & 3);
                float v0 = acc[mt][nt][ri * 2 + 0];
                float v1 = acc[mt][nt][ri * 2 + 1];
                if (mode == 0) {
                    *(float2*)(C + (size_t)m * DM + n) = make_float2(v0, v1);
                } else {
                    if (mode == 2) {
                        const int d = n & 63;   // even
                        // 10000^(-d/64) = exp2(-d * log2(1e4)/64)
                        const float inv = exp2f((float)d * -0.20762050f);
                        float sn, cs;
                        sincosf((float)m * inv, &sn, &cs);
                        const float a = v0, b = v1;
                        v0 = (a * cs - b * sn) * oscale;
                        v1 = (b * cs + a * sn) * oscale;
                    }
                    const int hh = n >> 6;
                    const int d0 = n & 63;
                    const size_t off = ((size_t)hh * SEQ + m) * DK + d0;
                    uint32_t h, l;
                    split2(v0, v1, h, l);
                    *(uint32_t*)(Ch + off) = h;
                    *(uint32_t*)(Cl + off) = l;
                }
            }
        }
}

// ---------------------------------------------------------------------------
// FA2-style flash attention, causal, fp16 mma.
// Br=128 (8 warps x 16 rows), Bc=64, 2 CTAs/SM.
// Q pre-scaled by 0.125*log2e at projection; softmax uses exp2f.
// S = QK^T: 3-term (Qh,Ql x Kh,Kl). PV: V is plain fp16 (hi only), P split
// hi/lo in registers -> 2-term. Causal mask hoisted to the last 2 iterations.
// ---------------------------------------------------------------------------
#define F_K0  0        // 64x144B hi + lo(+9216)
#define F_K1  18432
#define F_V0  36864    // hi only
#define F_V1  46080
#define F_Q   55296    // 128x144B hi + lo(+18432)
#define F_TOT 92160

__global__ void __launch_bounds__(256, 2)
flash_tc(const __half* __restrict__ qh, const __half* __restrict__ ql,
         const __half* __restrict__ kh, const __half* __restrict__ kl,
         const __half* __restrict__ vh,
         __half* __restrict__ aoh, __half* __restrict__ aol)
{
    extern __shared__ __align__(128) char sma[];
    const uint32_t sbase = s2u(sma);

    const int h    = blockIdx.y;
    const int qb   = gridDim.x - 1 - blockIdx.x;   // heavy tiles first
    const int tid  = threadIdx.x;
    const int lane = tid & 31;
    const int wid  = tid >> 5;
    const int wm   = wid * 16;
    const int g    = lane >> 2;
    const int tq   = lane & 3;

    const size_t hb = (size_t)h * SEQ * DK;
    const int nkb = 2 * qb + 2;     // number of 64-token blocks

    // ---- prologue: Q (group), K0+V0 (group) ----
    {
        const __half* qgh = qh + hb + (size_t)qb * 128 * DK;
        const __half* qgl = ql + hb + (size_t)qb * 128 * DK;
#pragma unroll
        for (int i = 0; i < 4; ++i) {
            const int idx = i * 256 + tid;
            const int r = idx >> 3;
            const int c = idx & 7;
            cp16(sbase + F_Q + r * 144 + c * 16, qgh + r * 64 + c * 8);
            cp16(sbase + F_Q + 18432 + r * 144 + c * 16, qgl + r * 64 + c * 8);
        }
        CP_COMMIT;
        const __half* kgh = kh + hb;
        const __half* kgl = kl + hb;
        const __half* vgh = vh + hb;
#pragma unroll
        for (int i = 0; i < 2; ++i) {
            const int idx = i * 256 + tid;
            const int r = idx >> 3;        // 0..63
            const int c = idx & 7;
            cp16(sbase + F_K0 + r * 144 + c * 16, kgh + r * 64 + c * 8);
            cp16(sbase + F_K0 + 9216 + r * 144 + c * 16, kgl + r * 64 + c * 8);
            cp16(sbase + F_V0 + r * 144 + c * 16, vgh + r * 64 + c * 8);
        }
        CP_COMMIT;
    }
    CP_WAIT1;
    __syncthreads();

    // ---- Q fragments (resident all kernel) ----
    uint32_t qfh[4][4], qfl[4][4];
#pragma unroll
    for (int d16 = 0; d16 < 4; ++d16) {
        const uint32_t ad = sbase + F_Q +
            ((wm + (lane & 15)) * 72 + d16 * 16 + (lane >> 4) * 8) * 2;
        ldsm4(qfh[d16], ad);
        ldsm4(qfl[d16], ad + 18432);
    }

    float oacc[8][4] = {};
    float mrow[2] = { -1e30f, -1e30f };
    float lrow[2] = { 0.f, 0.f };

    auto body = [&](int kb, bool domask) {
        __syncthreads();

        // prefetch K,V (kb+1)
        if (kb + 1 < nkb) {
            const __half* kgh = kh + hb + (size_t)(kb + 1) * 64 * DK;
            const __half* kgl = kl + hb + (size_t)(kb + 1) * 64 * DK;
            const __half* vgh = vh + hb + (size_t)(kb + 1) * 64 * DK;
            const uint32_t kB = sbase + (((kb + 1) & 1) ? F_K1 : F_K0);
            const uint32_t vB = sbase + (((kb + 1) & 1) ? F_V1 : F_V0);
#pragma unroll
            for (int i = 0; i < 2; ++i) {
                const int idx = i * 256 + tid;
                const int r = idx >> 3;
                const int c = idx & 7;
                cp16(kB + r * 144 + c * 16, kgh + r * 64 + c * 8);
                cp16(kB + 9216 + r * 144 + c * 16, kgl + r * 64 + c * 8);
                cp16(vB + r * 144 + c * 16, vgh + r * 64 + c * 8);
            }
        }
        CP_COMMIT;
        CP_WAIT1;
        __syncthreads();

        const uint32_t kBuf = sbase + ((kb & 1) ? F_K1 : F_K0);
        const uint32_t vBuf = sbase + ((kb & 1) ? F_V1 : F_V0);

        // ---- S = Q K^T (3-term) ----
        float sacc[8][4] = {};
#pragma unroll
        for (int d16 = 0; d16 < 4; ++d16) {
#pragma unroll
            for (int ng = 0; ng < 4; ++ng) {
                uint32_t bh[4], bl[4];
                const uint32_t ad = kBuf +
                    ((ng * 16 + (lane & 15)) * 72 + d16 * 16 + (lane >> 4) * 8) * 2;
                ldsm4(bh, ad);
                ldsm4(bl, ad + 9216);
                mma16816(sacc[2 * ng],     qfh[d16], bh[0], bh[2]);
                mma16816(sacc[2 * ng],     qfh[d16], bl[0], bl[2]);
                mma16816(sacc[2 * ng],     qfl[d16], bh[0], bh[2]);
                mma16816(sacc[2 * ng + 1], qfh[d16], bh[1], bh[3]);
                mma16816(sacc[2 * ng + 1], qfh[d16], bl[1], bl[3]);
                mma16816(sacc[2 * ng + 1], qfl[d16], bh[1], bh[3]);
            }
        }

        // ---- warp-local online softmax (log2 domain; scale folded in Q) ----
        const int moff = (kb - 2 * qb) * 64;    // used only when domask
        float corr[2];
#pragma unroll
        for (int hf = 0; hf < 2; ++hf) {
            const int rloc = wm + g + hf * 8;
            float vmax = -1e30f;
#pragma unroll
            for (int j = 0; j < 8; ++j)
#pragma unroll
                for (int ci = 0; ci < 2; ++ci) {
                    float v = sacc[j][hf * 2 + ci];
                    if (domask && (moff + 8 * j + 2 * tq + ci) > rloc) {
                        v = -1e30f;
                        sacc[j][hf * 2 + ci] = v;
                    }
                    vmax = fmaxf(vmax, v);
                }
            vmax = fmaxf(vmax, __shfl_xor_sync(0xffffffffu, vmax, 1));
            vmax = fmaxf(vmax, __shfl_xor_sync(0xffffffffu, vmax, 2));
            const float mnew = fmaxf(mrow[hf], vmax);
            corr[hf] = exp2f(mrow[hf] - mnew);
            mrow[hf] = mnew;
            float rs = 0.f;
#pragma unroll
            for (int j = 0; j < 8; ++j)
#pragma unroll
                for (int ci = 0; ci < 2; ++ci) {
                    const float p = exp2f(sacc[j][hf * 2 + ci] - mnew);
                    sacc[j][hf * 2 + ci] = p;
                    rs += p;
                }
            rs += __shfl_xor_sync(0xffffffffu, rs, 1);
            rs += __shfl_xor_sync(0xffffffffu, rs, 2);
            lrow[hf] = lrow[hf] * corr[hf] + rs;
#pragma unroll
            for (int j = 0; j < 8; ++j) {
                oacc[j][hf * 2 + 0] *= corr[hf];
                oacc[j][hf * 2 + 1] *= corr[hf];
            }
        }

        // ---- O += P V (2-term: Ph*Vh + Pl*Vh; V plain fp16) ----
#pragma unroll
        for (int kt = 0; kt < 4; ++kt) {
            uint32_t ah[4], al[4];
            split2(sacc[2 * kt][0],     sacc[2 * kt][1],     ah[0], al[0]);
            split2(sacc[2 * kt][2],     sacc[2 * kt][3],     ah[1], al[1]);
            split2(sacc[2 * kt + 1][0], sacc[2 * kt + 1][1], ah[2], al[2]);
            split2(sacc[2 * kt + 1][2], sacc[2 * kt + 1][3], ah[3], al[3]);
            const int t_loc = kt * 16 + (lane & 7) + ((lane >> 3) & 1) * 8;
#pragma unroll
            for (int ng = 0; ng < 4; ++ng) {
                uint32_t bh[4];
                const int d_loc = ng * 16 + ((lane >> 4) & 1) * 8;
                const uint32_t ad = vBuf + (uint32_t)(t_loc * 72 + d_loc) * 2;
                ldsm4t(bh, ad);
                mma16816(oacc[2 * ng],     ah, bh[0], bh[1]);
                mma16816(oacc[2 * ng],     al, bh[0], bh[1]);
                mma16816(oacc[2 * ng + 1], ah, bh[2], bh[3]);
                mma16816(oacc[2 * ng + 1], al, bh[2], bh[3]);
            }
        }
    };

    for (int kb = 0; kb < nkb - 2; ++kb) body(kb, false);
    body(nkb - 2, true);
    body(nkb - 1, true);

    // ---- epilogue ----
#pragma unroll
    for (int hf = 0; hf < 2; ++hf) {
        const float inv = 1.f / lrow[hf];
        const int q = qb * 128 + wm + g + hf * 8;
#pragma unroll
        for (int j = 0; j < 8; ++j) {
            const float v0 = oacc[j][hf * 2 + 0] * inv;
            const float v1 = oacc[j][hf * 2 + 1] * inv;
            const int col = h * 64 + 8 * j + 2 * tq;
            uint32_t hw, lw;
            split2(v0, v1, hw, lw);
            *(uint32_t*)(aoh + (size_t)q * DM + col) = hw;
            *(uint32_t*)(aol + (size_t)q * DM + col) = lw;
        }
    }
}

// ---------------------------------------------------------------------------
extern "C" void kernel_launch(void* const* d_in, const int* in_sizes, int n_in,
                              void* d_out, int out_size)
{
    const float* x  = (const float*)d_in[0];
    const float* Wq = (const float*)d_in[1];
    const float* Wk = (const float*)d_in[2];
    const float* Wv = (const float*)d_in[3];
    const float* Wo = (const float*)d_in[4];

    __half *xh, *xl, *wh, *wl, *qhp, *qlp, *khp, *klp, *vhp, *aoh, *aol;
    cudaGetSymbolAddress((void**)&xh,  g_xh);
    cudaGetSymbolAddress((void**)&xl,  g_xl);
    cudaGetSymbolAddress((void**)&wh,  g_wh);
    cudaGetSymbolAddress((void**)&wl,  g_wl);
    cudaGetSymbolAddress((void**)&qhp, g_qh);
    cudaGetSymbolAddress((void**)&qlp, g_ql);
    cudaGetSymbolAddress((void**)&khp, g_kh);
    cudaGetSymbolAddress((void**)&klp, g_kl);
    cudaGetSymbolAddress((void**)&vhp, g_vh);
    cudaGetSymbolAddress((void**)&aoh, g_aoh);
    cudaGetSymbolAddress((void**)&aol, g_aol);

    const int nx2 = SEQ * DM / 2;
    const int nw2 = DM * DM / 2;
    split_bf16<<<(nx2 + 255) / 256, 256>>>(x, xh, xl, nx2);
    split4_bf16<<<dim3((nw2 + 255) / 256, 4), 256>>>(Wq, Wk, Wv, Wo, wh, wl, nw2);

    const int gsm = 2 * 4 * 10240;   // 81,920 B
    cudaFuncSetAttribute(gemm_mma, cudaFuncAttributeMaxDynamicSharedMemorySize, gsm);
    cudaFuncSetAttribute(flash_tc, cudaFuncAttributeMaxDynamicSharedMemorySize, F_TOT);

    // fused Q/K/V projections (Q pre-scaled by 0.125*log2e). V lo is unused
    // by flash; reuse xl slot... keep a distinct dummy: write V lo into aol
    // (overwritten later by flash epilogue anyway -> harmless).
    gemm_mma<<<dim3(DM / 128, SEQ / 128, 3), 256, gsm>>>(
        xh, xl, wh, wl, nullptr, qhp, qlp, khp, klp, vhp, aol, 1);

    flash_tc<<<dim3(SEQ / 128, NH), 256, F_TOT>>>(qhp, qlp, khp, klp, vhp, aoh, aol);

    // Wo projection
    gemm_mma<<<dim3(DM / 128, SEQ / 128, 1), 256, gsm>>>(
        aoh, aol, wh, wl, (float*)d_out,
        nullptr, nullptr, nullptr, nullptr, nullptr, nullptr, 0);
}

// round 10
// speedup vs baseline: 3.9547x; 1.1217x over previous
#include <cuda_runtime.h>
#include <cuda_fp16.h>
#include <math.h>
#include <stdint.h>

#define SEQ 4096
#define DM  1024
#define NH  16
#define DK  64

// ---------------------------------------------------------------------------
// scratch (no allocs allowed) — fp16 hi/lo pairs (V consumed hi-only)
// ---------------------------------------------------------------------------
__device__ __half g_xh [SEQ * DM];
__device__ __half g_xl [SEQ * DM];
__device__ __half g_wh [4][DM * DM];
__device__ __half g_wl [4][DM * DM];
__device__ __half g_qh [NH * SEQ * DK];
__device__ __half g_ql [NH * SEQ * DK];
__device__ __half g_kh [NH * SEQ * DK];
__device__ __half g_kl [NH * SEQ * DK];
__device__ __half g_vh [NH * SEQ * DK];
__device__ __half g_aoh[SEQ * DM];
__device__ __half g_aol[SEQ * DM];

// ---------------------------------------------------------------------------
// helpers
// ---------------------------------------------------------------------------
static __device__ __forceinline__ uint32_t s2u(const void* p) {
    uint32_t a;
    asm("{ .reg .u64 t; cvta.to.shared.u64 t, %1; cvt.u32.u64 %0, t; }"
        : "=r"(a) : "l"(p));
    return a;
}
static __device__ __forceinline__ void ldsm4(uint32_t* r, uint32_t addr) {
    asm volatile("ldmatrix.sync.aligned.m8n8.x4.shared.b16 {%0,%1,%2,%3}, [%4];"
                 : "=r"(r[0]), "=r"(r[1]), "=r"(r[2]), "=r"(r[3]) : "r"(addr));
}
static __device__ __forceinline__ void ldsm4t(uint32_t* r, uint32_t addr) {
    asm volatile("ldmatrix.sync.aligned.m8n8.x4.trans.shared.b16 {%0,%1,%2,%3}, [%4];"
                 : "=r"(r[0]), "=r"(r[1]), "=r"(r[2]), "=r"(r[3]) : "r"(addr));
}
static __device__ __forceinline__ void mma16816(float* d, const uint32_t* a,
                                                uint32_t b0, uint32_t b1) {
    asm volatile(
        "mma.sync.aligned.m16n8k16.row.col.f32.f16.f16.f32 "
        "{%0,%1,%2,%3},{%4,%5,%6,%7},{%8,%9},{%0,%1,%2,%3};"
        : "+f"(d[0]), "+f"(d[1]), "+f"(d[2]), "+f"(d[3])
        : "r"(a[0]), "r"(a[1]), "r"(a[2]), "r"(a[3]), "r"(b0), "r"(b1));
}
static __device__ __forceinline__ void cp16(uint32_t s, const void* g) {
    asm volatile("cp.async.cg.shared.global [%0], [%1], 16;" :: "r"(s), "l"(g));
}
#define CP_COMMIT asm volatile("cp.async.commit_group;")
#define CP_WAIT0  asm volatile("cp.async.wait_group 0;")
#define CP_WAIT1  asm volatile("cp.async.wait_group 1;")

static __device__ __forceinline__ uint32_t pack_h2(__half a, __half b) {
    __half2 t = __halves2half2(a, b);
    return *reinterpret_cast<uint32_t*>(&t);
}
static __device__ __forceinline__ void split2(float v0, float v1,
                                              uint32_t& hi, uint32_t& lo) {
    __half h0 = __float2half_rn(v0);
    __half h1 = __float2half_rn(v1);
    __half l0 = __float2half_rn(v0 - __half2float(h0));
    __half l1 = __float2half_rn(v1 - __half2float(h1));
    hi = pack_h2(h0, h1);
    lo = pack_h2(l0, l1);
}

// ---------------------------------------------------------------------------
// split fp32 -> fp16 (hi, lo)
// ---------------------------------------------------------------------------
__global__ void __launch_bounds__(256)
split_bf16(const float* __restrict__ src, __half* __restrict__ hi,
           __half* __restrict__ lo, int n2)
{
    int i = blockIdx.x * 256 + threadIdx.x;
    if (i >= n2) return;
    float2 v = ((const float2*)src)[i];
    uint32_t h, l;
    split2(v.x, v.y, h, l);
    ((uint32_t*)hi)[i] = h;
    ((uint32_t*)lo)[i] = l;
}

__global__ void __launch_bounds__(256)
split4_bf16(const float* __restrict__ s0, const float* __restrict__ s1,
            const float* __restrict__ s2, const float* __restrict__ s3,
            __half* __restrict__ hi, __half* __restrict__ lo, int n2)
{
    int i = blockIdx.x * 256 + threadIdx.x;
    if (i >= n2) return;
    const int y = blockIdx.y;
    const float* s = (y == 0) ? s0 : (y == 1) ? s1 : (y == 2) ? s2 : s3;
    float2 v = ((const float2*)s)[i];
    uint32_t h, l;
    split2(v.x, v.y, h, l);
    const size_t base = (size_t)y * (DM * DM / 2);
    ((uint32_t*)hi)[base + i] = h;
    ((uint32_t*)lo)[base + i] = l;
}

// ---------------------------------------------------------------------------
// mma.sync fp16 GEMM. 128x128x32 tiles, cp.async double-buffered,
// 8 warps (2m x 4n), 2 CTAs/SM. Q output (z==0) pre-scaled by 0.125*log2(e).
// Q,K projections: 3-term (Ah·Bh + Ah·Bl + Al·Bh).
// V projection & Wo: 2-term (Ah·Bh + Al·Bh) — Bl skipped (load + mma).
// ---------------------------------------------------------------------------
__global__ void __launch_bounds__(256, 2)
gemm_mma(const __half* __restrict__ Ah_g, const __half* __restrict__ Al_g,
         const __half* __restrict__ WhAll, const __half* __restrict__ WlAll,
         float* __restrict__ C,
         __half* __restrict__ C0h, __half* __restrict__ C0l,
         __half* __restrict__ C1h, __half* __restrict__ C1l,
         __half* __restrict__ C2h, __half* __restrict__ C2l,
         int qkv)
{
    constexpr int K = DM;
    constexpr int TILE  = 10240;   // 128 rows x 40 fp16 (pitch 80B)
    constexpr int STAGE = 4 * TILE;
    extern __shared__ __align__(128) char smg[];
    const uint32_t sbase = s2u(smg);

    const int z   = blockIdx.z;
    const int mode = qkv ? ((z == 2) ? 1 : 2) : 0;
    const bool useBl = qkv && (z < 2);     // 3-term only for Q,K
    const float oscale = (qkv && z == 0) ? 0.125f * 1.44269504f : 1.0f;
    const size_t wsel = qkv ? (size_t)z * DM * DM : (size_t)3 * DM * DM;
    const __half* Bh_g = WhAll + wsel;
    const __half* Bl_g = WlAll + wsel;
    __half* Ch = (z == 0) ? C0h : (z == 1) ? C1h : C2h;
    __half* Cl = (z == 0) ? C0l : (z == 1) ? C1l : C2l;

    const int bm  = blockIdx.y * 128;
    const int bn  = blockIdx.x * 128;
    const int tid = threadIdx.x;
    const int lane = tid & 31;
    const int wid  = tid >> 5;
    const int wm = (wid >> 2) * 64;
    const int wn = (wid & 3) * 32;

    const __half* srcs[4] = {
        Ah_g + (size_t)bm * K, Al_g + (size_t)bm * K,
        Bh_g + (size_t)bn * K, Bl_g + (size_t)bn * K };

    const int ntile = useBl ? 4 : 3;
    auto fill = [&](int s, int kc) {
#pragma unroll
        for (int t = 0; t < 4; ++t) {
            if (t >= ntile) break;
#pragma unroll
            for (int i = 0; i < 2; ++i) {
                const int idx = i * 256 + tid;
                const int r = idx >> 2;
                const int c = idx & 3;
                cp16(sbase + s * STAGE + t * TILE + r * 80 + c * 16,
                     srcs[t] + (size_t)r * K + kc * 32 + c * 8);
            }
        }
        CP_COMMIT;
    };

    float acc[4][4][4] = {};

    fill(0, 0);
    for (int kc = 0; kc < K / 32; ++kc) {
        CP_WAIT0;
        __syncthreads();
        if (kc + 1 < K / 32) fill((kc + 1) & 1, kc + 1);

        const uint32_t aB = sbase + (kc & 1) * STAGE;
        const uint32_t bB = aB + 2 * TILE;
#pragma unroll
        for (int ks = 0; ks < 2; ++ks) {
            uint32_t ah[4][4], al[4][4];
#pragma unroll
            for (int mt = 0; mt < 4; ++mt) {
                const uint32_t ad = aB +
                    ((wm + mt * 16 + (lane & 15)) * 40 + ks * 16 + (lane >> 4) * 8) * 2;
                ldsm4(ah[mt], ad);
                ldsm4(al[mt], ad + TILE);
            }
#pragma unroll
            for (int np = 0; np < 2; ++np) {
                uint32_t bh[4], bl[4];
                const uint32_t ad = bB +
                    ((wn + np * 16 + (lane & 15)) * 40 + ks * 16 + (lane >> 4) * 8) * 2;
                ldsm4(bh, ad);
                if (useBl) ldsm4(bl, ad + TILE);
#pragma unroll
                for (int mt = 0; mt < 4; ++mt)
#pragma unroll
                    for (int hf = 0; hf < 2; ++hf) {
                        float* a4 = acc[mt][np * 2 + hf];
                        mma16816(a4, ah[mt], bh[hf], bh[hf + 2]);
                        if (useBl) mma16816(a4, ah[mt], bl[hf], bl[hf + 2]);
                        mma16816(a4, al[mt], bh[hf], bh[hf + 2]);
                    }
            }
        }
        __syncthreads();
    }

#pragma unroll
    for (int mt = 0; mt < 4; ++mt)
#pragma unroll
        for (int ri = 0; ri < 2; ++ri) {
            const int m = bm + wm + mt * 16 + ri * 8 + (lane >> 2);
#pragma unroll
            for (int nt = 0; nt < 4; ++nt) {
                const int n = bn + wn + nt * 8 + 2 * (lane & 3);
                float v0 = acc[mt][nt][ri * 2 + 0];
                float v1 = acc[mt][nt][ri * 2 + 1];
                if (mode == 0) {
                    *(float2*)(C + (size_t)m * DM + n) = make_float2(v0, v1);
                } else {
                    if (mode == 2) {
                        const int d = n & 63;   // even
                        const float inv = exp2f((float)d * -0.20762050f);
                        float sn, cs;
                        sincosf((float)m * inv, &sn, &cs);
                        const float a = v0, b = v1;
                        v0 = (a * cs - b * sn) * oscale;
                        v1 = (b * cs + a * sn) * oscale;
                    }
                    const int hh = n >> 6;
                    const int d0 = n & 63;
                    const size_t off = ((size_t)hh * SEQ + m) * DK + d0;
                    uint32_t h, l;
                    split2(v0, v1, h, l);
                    *(uint32_t*)(Ch + off) = h;
                    *(uint32_t*)(Cl + off) = l;
                }
            }
        }
}

// ---------------------------------------------------------------------------
// FA2-style flash attention, causal, fp16 mma.
// Br=128 (8 warps x 16 rows), Bc=64, 2 CTAs/SM.
// Q pre-scaled by 0.125*log2e; softmax in log2 domain (exp2f).
// S = QK^T: 3-term. PV: P and V both single fp16 -> 1-term per n8 pair.
// Causal mask hoisted to the last 2 iterations.
// ---------------------------------------------------------------------------
#define F_K0  0        // 64x144B hi + lo(+9216)
#define F_K1  18432
#define F_V0  36864    // hi only
#define F_V1  46080
#define F_Q   55296    // 128x144B hi + lo(+18432)
#define F_TOT 92160

__global__ void __launch_bounds__(256, 2)
flash_tc(const __half* __restrict__ qh, const __half* __restrict__ ql,
         const __half* __restrict__ kh, const __half* __restrict__ kl,
         const __half* __restrict__ vh,
         __half* __restrict__ aoh, __half* __restrict__ aol)
{
    extern __shared__ __align__(128) char sma[];
    const uint32_t sbase = s2u(sma);

    const int h    = blockIdx.y;
    const int qb   = gridDim.x - 1 - blockIdx.x;   // heavy tiles first
    const int tid  = threadIdx.x;
    const int lane = tid & 31;
    const int wid  = tid >> 5;
    const int wm   = wid * 16;
    const int g    = lane >> 2;
    const int tq   = lane & 3;

    const size_t hb = (size_t)h * SEQ * DK;
    const int nkb = 2 * qb + 2;     // number of 64-token blocks

    // ---- prologue: Q (group), K0+V0 (group) ----
    {
        const __half* qgh = qh + hb + (size_t)qb * 128 * DK;
        const __half* qgl = ql + hb + (size_t)qb * 128 * DK;
#pragma unroll
        for (int i = 0; i < 4; ++i) {
            const int idx = i * 256 + tid;
            const int r = idx >> 3;
            const int c = idx & 7;
            cp16(sbase + F_Q + r * 144 + c * 16, qgh + r * 64 + c * 8);
            cp16(sbase + F_Q + 18432 + r * 144 + c * 16, qgl + r * 64 + c * 8);
        }
        CP_COMMIT;
        const __half* kgh = kh + hb;
        const __half* kgl = kl + hb;
        const __half* vgh = vh + hb;
#pragma unroll
        for (int i = 0; i < 2; ++i) {
            const int idx = i * 256 + tid;
            const int r = idx >> 3;        // 0..63
            const int c = idx & 7;
            cp16(sbase + F_K0 + r * 144 + c * 16, kgh + r * 64 + c * 8);
            cp16(sbase + F_K0 + 9216 + r * 144 + c * 16, kgl + r * 64 + c * 8);
            cp16(sbase + F_V0 + r * 144 + c * 16, vgh + r * 64 + c * 8);
        }
        CP_COMMIT;
    }
    CP_WAIT1;
    __syncthreads();

    // ---- Q fragments (resident all kernel) ----
    uint32_t qfh[4][4], qfl[4][4];
#pragma unroll
    for (int d16 = 0; d16 < 4; ++d16) {
        const uint32_t ad = sbase + F_Q +
            ((wm + (lane & 15)) * 72 + d16 * 16 + (lane >> 4) * 8) * 2;
        ldsm4(qfh[d16], ad);
        ldsm4(qfl[d16], ad + 18432);
    }

    float oacc[8][4] = {};
    float mrow[2] = { -1e30f, -1e30f };
    float lrow[2] = { 0.f, 0.f };

    auto body = [&](int kb, bool domask) {
        __syncthreads();

        // prefetch K,V (kb+1)
        if (kb + 1 < nkb) {
            const __half* kgh = kh + hb + (size_t)(kb + 1) * 64 * DK;
            const __half* kgl = kl + hb + (size_t)(kb + 1) * 64 * DK;
            const __half* vgh = vh + hb + (size_t)(kb + 1) * 64 * DK;
            const uint32_t kB = sbase + (((kb + 1) & 1) ? F_K1 : F_K0);
            const uint32_t vB = sbase + (((kb + 1) & 1) ? F_V1 : F_V0);
#pragma unroll
            for (int i = 0; i < 2; ++i) {
                const int idx = i * 256 + tid;
                const int r = idx >> 3;
                const int c = idx & 7;
                cp16(kB + r * 144 + c * 16, kgh + r * 64 + c * 8);
                cp16(kB + 9216 + r * 144 + c * 16, kgl + r * 64 + c * 8);
                cp16(vB + r * 144 + c * 16, vgh + r * 64 + c * 8);
            }
        }
        CP_COMMIT;
        CP_WAIT1;
        __syncthreads();

        const uint32_t kBuf = sbase + ((kb & 1) ? F_K1 : F_K0);
        const uint32_t vBuf = sbase + ((kb & 1) ? F_V1 : F_V0);

        // ---- S = Q K^T (3-term) ----
        float sacc[8][4] = {};
#pragma unroll
        for (int d16 = 0; d16 < 4; ++d16) {
#pragma unroll
            for (int ng = 0; ng < 4; ++ng) {
                uint32_t bh[4], bl[4];
                const uint32_t ad = kBuf +
                    ((ng * 16 + (lane & 15)) * 72 + d16 * 16 + (lane >> 4) * 8) * 2;
                ldsm4(bh, ad);
                ldsm4(bl, ad + 9216);
                mma16816(sacc[2 * ng],     qfh[d16], bh[0], bh[2]);
                mma16816(sacc[2 * ng],     qfh[d16], bl[0], bl[2]);
                mma16816(sacc[2 * ng],     qfl[d16], bh[0], bh[2]);
                mma16816(sacc[2 * ng + 1], qfh[d16], bh[1], bh[3]);
                mma16816(sacc[2 * ng + 1], qfh[d16], bl[1], bl[3]);
                mma16816(sacc[2 * ng + 1], qfl[d16], bh[1], bh[3]);
            }
        }

        // ---- warp-local online softmax (log2 domain) ----
        const int moff = (kb - 2 * qb) * 64;    // used only when domask
        float corr[2];
#pragma unroll
        for (int hf = 0; hf < 2; ++hf) {
            const int rloc = wm + g + hf * 8;
            float vmax = -1e30f;
#pragma unroll
            for (int j = 0; j < 8; ++j)
#pragma unroll
                for (int ci = 0; ci < 2; ++ci) {
                    float v = sacc[j][hf * 2 + ci];
                    if (domask && (moff + 8 * j + 2 * tq + ci) > rloc) {
                        v = -1e30f;
                        sacc[j][hf * 2 + ci] = v;
                    }
                    vmax = fmaxf(vmax, v);
                }
            vmax = fmaxf(vmax, __shfl_xor_sync(0xffffffffu, vmax, 1));
            vmax = fmaxf(vmax, __shfl_xor_sync(0xffffffffu, vmax, 2));
            const float mnew = fmaxf(mrow[hf], vmax);
            corr[hf] = exp2f(mrow[hf] - mnew);
            mrow[hf] = mnew;
            float rs = 0.f;
#pragma unroll
            for (int j = 0; j < 8; ++j)
#pragma unroll
                for (int ci = 0; ci < 2; ++ci) {
                    const float p = exp2f(sacc[j][hf * 2 + ci] - mnew);
                    sacc[j][hf * 2 + ci] = p;
                    rs += p;
                }
            rs += __shfl_xor_sync(0xffffffffu, rs, 1);
            rs += __shfl_xor_sync(0xffffffffu, rs, 2);
            lrow[hf] = lrow[hf] * corr[hf] + rs;
#pragma unroll
            for (int j = 0; j < 8; ++j) {
                oacc[j][hf * 2 + 0] *= corr[hf];
                oacc[j][hf * 2 + 1] *= corr[hf];
            }
        }

        // ---- O += P V (P single fp16, V single fp16) ----
#pragma unroll
        for (int kt = 0; kt < 4; ++kt) {
            uint32_t ah[4];
            ah[0] = pack_h2(__float2half_rn(sacc[2 * kt][0]),
                            __float2half_rn(sacc[2 * kt][1]));
            ah[1] = pack_h2(__float2half_rn(sacc[2 * kt][2]),
                            __float2half_rn(sacc[2 * kt][3]));
            ah[2] = pack_h2(__float2half_rn(sacc[2 * kt + 1][0]),
                            __float2half_rn(sacc[2 * kt + 1][1]));
            ah[3] = pack_h2(__float2half_rn(sacc[2 * kt + 1][2]),
                            __float2half_rn(sacc[2 * kt + 1][3]));
            const int t_loc = kt * 16 + (lane & 7) + ((lane >> 3) & 1) * 8;
#pragma unroll
            for (int ng = 0; ng < 4; ++ng) {
                uint32_t bh[4];
                const int d_loc = ng * 16 + ((lane >> 4) & 1) * 8;
                const uint32_t ad = vBuf + (uint32_t)(t_loc * 72 + d_loc) * 2;
                ldsm4t(bh, ad);
                mma16816(oacc[2 * ng],     ah, bh[0], bh[1]);
                mma16816(oacc[2 * ng + 1], ah, bh[2], bh[3]);
            }
        }
    };

    for (int kb = 0; kb < nkb - 2; ++kb) body(kb, false);
    body(nkb - 2, true);
    body(nkb - 1, true);

    // ---- epilogue ----
#pragma unroll
    for (int hf = 0; hf < 2; ++hf) {
        const float inv = 1.f / lrow[hf];
        const int q = qb * 128 + wm + g + hf * 8;
#pragma unroll
        for (int j = 0; j < 8; ++j) {
            const float v0 = oacc[j][hf * 2 + 0] * inv;
            const float v1 = oacc[j][hf * 2 + 1] * inv;
            const int col = h * 64 + 8 * j + 2 * tq;
            uint32_t hw, lw;
            split2(v0, v1, hw, lw);
            *(uint32_t*)(aoh + (size_t)q * DM + col) = hw;
            *(uint32_t*)(aol + (size_t)q * DM + col) = lw;
        }
    }
}

// ---------------------------------------------------------------------------
extern "C" void kernel_launch(void* const* d_in, const int* in_sizes, int n_in,
                              void* d_out, int out_size)
{
    const float* x  = (const float*)d_in[0];
    const float* Wq = (const float*)d_in[1];
    const float* Wk = (const float*)d_in[2];
    const float* Wv = (const float*)d_in[3];
    const float* Wo = (const float*)d_in[4];

    __half *xh, *xl, *wh, *wl, *qhp, *qlp, *khp, *klp, *vhp, *aoh, *aol;
    cudaGetSymbolAddress((void**)&xh,  g_xh);
    cudaGetSymbolAddress((void**)&xl,  g_xl);
    cudaGetSymbolAddress((void**)&wh,  g_wh);
    cudaGetSymbolAddress((void**)&wl,  g_wl);
    cudaGetSymbolAddress((void**)&qhp, g_qh);
    cudaGetSymbolAddress((void**)&qlp, g_ql);
    cudaGetSymbolAddress((void**)&khp, g_kh);
    cudaGetSymbolAddress((void**)&klp, g_kl);
    cudaGetSymbolAddress((void**)&vhp, g_vh);
    cudaGetSymbolAddress((void**)&aoh, g_aoh);
    cudaGetSymbolAddress((void**)&aol, g_aol);

    const int nx2 = SEQ * DM / 2;
    const int nw2 = DM * DM / 2;
    split_bf16<<<(nx2 + 255) / 256, 256>>>(x, xh, xl, nx2);
    split4_bf16<<<dim3((nw2 + 255) / 256, 4), 256>>>(Wq, Wk, Wv, Wo, wh, wl, nw2);

    const int gsm = 2 * 4 * 10240;   // 81,920 B
    cudaFuncSetAttribute(gemm_mma, cudaFuncAttributeMaxDynamicSharedMemorySize, gsm);
    cudaFuncSetAttribute(flash_tc, cudaFuncAttributeMaxDynamicSharedMemorySize, F_TOT);

    // fused Q/K/V projections (Q pre-scaled by 0.125*log2e); V lo -> dummy
    // target aol, fully overwritten by flash epilogue afterwards.
    gemm_mma<<<dim3(DM / 128, SEQ / 128, 3), 256, gsm>>>(
        xh, xl, wh, wl, nullptr, qhp, qlp, khp, klp, vhp, aol, 1);

    flash_tc<<<dim3(SEQ / 128, NH), 256, F_TOT>>>(qhp, qlp, khp, klp, vhp, aoh, aol);

    // Wo projection (2-term, weights hi only)
    gemm_mma<<<dim3(DM / 128, SEQ / 128, 1), 256, gsm>>>(
        aoh, aol, wh, wl, (float*)d_out,
        nullptr, nullptr, nullptr, nullptr, nullptr, nullptr, 0);
}

// round 11
// speedup vs baseline: 4.4252x; 1.1190x over previous
#include <cuda_runtime.h>
#include <cuda_fp16.h>
#include <math.h>
#include <stdint.h>

#define SEQ 4096
#define DM  1024
#define NH  16
#define DK  64

// ---------------------------------------------------------------------------
// scratch (no allocs allowed) — fp16 hi/lo pairs (V consumed hi-only)
// ---------------------------------------------------------------------------
__device__ __half g_xh [SEQ * DM];
__device__ __half g_xl [SEQ * DM];
__device__ __half g_wh [4][DM * DM];
__device__ __half g_wl [4][DM * DM];
__device__ __half g_qh [NH * SEQ * DK];
__device__ __half g_ql [NH * SEQ * DK];
__device__ __half g_kh [NH * SEQ * DK];
__device__ __half g_kl [NH * SEQ * DK];
__device__ __half g_vh [NH * SEQ * DK];
__device__ __half g_aoh[SEQ * DM];
__device__ __half g_aol[SEQ * DM];

// ---------------------------------------------------------------------------
// helpers
// ---------------------------------------------------------------------------
static __device__ __forceinline__ uint32_t s2u(const void* p) {
    uint32_t a;
    asm("{ .reg .u64 t; cvta.to.shared.u64 t, %1; cvt.u32.u64 %0, t; }"
        : "=r"(a) : "l"(p));
    return a;
}
static __device__ __forceinline__ void ldsm4(uint32_t* r, uint32_t addr) {
    asm volatile("ldmatrix.sync.aligned.m8n8.x4.shared.b16 {%0,%1,%2,%3}, [%4];"
                 : "=r"(r[0]), "=r"(r[1]), "=r"(r[2]), "=r"(r[3]) : "r"(addr));
}
static __device__ __forceinline__ void ldsm4t(uint32_t* r, uint32_t addr) {
    asm volatile("ldmatrix.sync.aligned.m8n8.x4.trans.shared.b16 {%0,%1,%2,%3}, [%4];"
                 : "=r"(r[0]), "=r"(r[1]), "=r"(r[2]), "=r"(r[3]) : "r"(addr));
}
static __device__ __forceinline__ void ldsm2t(uint32_t* r, uint32_t addr) {
    asm volatile("ldmatrix.sync.aligned.m8n8.x2.trans.shared.b16 {%0,%1}, [%2];"
                 : "=r"(r[0]), "=r"(r[1]) : "r"(addr));
}
static __device__ __forceinline__ void mma16816(float* d, const uint32_t* a,
                                                uint32_t b0, uint32_t b1) {
    asm volatile(
        "mma.sync.aligned.m16n8k16.row.col.f32.f16.f16.f32 "
        "{%0,%1,%2,%3},{%4,%5,%6,%7},{%8,%9},{%0,%1,%2,%3};"
        : "+f"(d[0]), "+f"(d[1]), "+f"(d[2]), "+f"(d[3])
        : "r"(a[0]), "r"(a[1]), "r"(a[2]), "r"(a[3]), "r"(b0), "r"(b1));
}
static __device__ __forceinline__ void cp16(uint32_t s, const void* g) {
    asm volatile("cp.async.cg.shared.global [%0], [%1], 16;" :: "r"(s), "l"(g));
}
#define CP_COMMIT asm volatile("cp.async.commit_group;")
#define CP_WAIT0  asm volatile("cp.async.wait_group 0;")
#define CP_WAIT1  asm volatile("cp.async.wait_group 1;")

static __device__ __forceinline__ uint32_t pack_h2(__half a, __half b) {
    __half2 t = __halves2half2(a, b);
    return *reinterpret_cast<uint32_t*>(&t);
}
// pack two fp32 into half2 word: lo -> low half, hi -> high half
static __device__ __forceinline__ uint32_t cvt_h2(float lo, float hi) {
    uint32_t r;
    asm("cvt.rn.f16x2.f32 %0, %1, %2;" : "=r"(r) : "f"(hi), "f"(lo));
    return r;
}
static __device__ __forceinline__ uint32_t h2exp2(uint32_t x) {
    uint32_t r;
    asm("ex2.approx.f16x2 %0, %1;" : "=r"(r) : "r"(x));
    return r;
}
static __device__ __forceinline__ void split2(float v0, float v1,
                                              uint32_t& hi, uint32_t& lo) {
    __half h0 = __float2half_rn(v0);
    __half h1 = __float2half_rn(v1);
    __half l0 = __float2half_rn(v0 - __half2float(h0));
    __half l1 = __float2half_rn(v1 - __half2float(h1));
    hi = pack_h2(h0, h1);
    lo = pack_h2(l0, l1);
}

// ---------------------------------------------------------------------------
// split fp32 -> fp16 (hi, lo)
// ---------------------------------------------------------------------------
__global__ void __launch_bounds__(256)
split_bf16(const float* __restrict__ src, __half* __restrict__ hi,
           __half* __restrict__ lo, int n2)
{
    int i = blockIdx.x * 256 + threadIdx.x;
    if (i >= n2) return;
    float2 v = ((const float2*)src)[i];
    uint32_t h, l;
    split2(v.x, v.y, h, l);
    ((uint32_t*)hi)[i] = h;
    ((uint32_t*)lo)[i] = l;
}

__global__ void __launch_bounds__(256)
split4_bf16(const float* __restrict__ s0, const float* __restrict__ s1,
            const float* __restrict__ s2, const float* __restrict__ s3,
            __half* __restrict__ hi, __half* __restrict__ lo, int n2)
{
    int i = blockIdx.x * 256 + threadIdx.x;
    if (i >= n2) return;
    const int y = blockIdx.y;
    const float* s = (y == 0) ? s0 : (y == 1) ? s1 : (y == 2) ? s2 : s3;
    float2 v = ((const float2*)s)[i];
    uint32_t h, l;
    split2(v.x, v.y, h, l);
    const size_t base = (size_t)y * (DM * DM / 2);
    ((uint32_t*)hi)[base + i] = h;
    ((uint32_t*)lo)[base + i] = l;
}

// ---------------------------------------------------------------------------
// mma.sync fp16 GEMM. 128x128x32 tiles, cp.async double-buffered,
// 8 warps (2m x 4n), 2 CTAs/SM. Q output (z==0) pre-scaled by 0.125*log2(e).
// Q,K: 3-term. V & Wo: 2-term. mma issued term-major (same-acc distance 8).
// ---------------------------------------------------------------------------
__global__ void __launch_bounds__(256, 2)
gemm_mma(const __half* __restrict__ Ah_g, const __half* __restrict__ Al_g,
         const __half* __restrict__ WhAll, const __half* __restrict__ WlAll,
         float* __restrict__ C,
         __half* __restrict__ C0h, __half* __restrict__ C0l,
         __half* __restrict__ C1h, __half* __restrict__ C1l,
         __half* __restrict__ C2h, __half* __restrict__ C2l,
         int qkv)
{
    constexpr int K = DM;
    constexpr int TILE  = 10240;   // 128 rows x 40 fp16 (pitch 80B)
    constexpr int STAGE = 4 * TILE;
    extern __shared__ __align__(128) char smg[];
    const uint32_t sbase = s2u(smg);

    const int z   = blockIdx.z;
    const int mode = qkv ? ((z == 2) ? 1 : 2) : 0;
    const bool useBl = qkv && (z < 2);     // 3-term only for Q,K
    const float oscale = (qkv && z == 0) ? 0.125f * 1.44269504f : 1.0f;
    const size_t wsel = qkv ? (size_t)z * DM * DM : (size_t)3 * DM * DM;
    const __half* Bh_g = WhAll + wsel;
    const __half* Bl_g = WlAll + wsel;
    __half* Ch = (z == 0) ? C0h : (z == 1) ? C1h : C2h;
    __half* Cl = (z == 0) ? C0l : (z == 1) ? C1l : C2l;

    const int bm  = blockIdx.y * 128;
    const int bn  = blockIdx.x * 128;
    const int tid = threadIdx.x;
    const int lane = tid & 31;
    const int wid  = tid >> 5;
    const int wm = (wid >> 2) * 64;
    const int wn = (wid & 3) * 32;

    const __half* srcs[4] = {
        Ah_g + (size_t)bm * K, Al_g + (size_t)bm * K,
        Bh_g + (size_t)bn * K, Bl_g + (size_t)bn * K };

    const int ntile = useBl ? 4 : 3;
    auto fill = [&](int s, int kc) {
#pragma unroll
        for (int t = 0; t < 4; ++t) {
            if (t >= ntile) break;
#pragma unroll
            for (int i = 0; i < 2; ++i) {
                const int idx = i * 256 + tid;
                const int r = idx >> 2;
                const int c = idx & 3;
                cp16(sbase + s * STAGE + t * TILE + r * 80 + c * 16,
                     srcs[t] + (size_t)r * K + kc * 32 + c * 8);
            }
        }
        CP_COMMIT;
    };

    float acc[4][4][4] = {};

    fill(0, 0);
    for (int kc = 0; kc < K / 32; ++kc) {
        CP_WAIT0;
        __syncthreads();
        if (kc + 1 < K / 32) fill((kc + 1) & 1, kc + 1);

        const uint32_t aB = sbase + (kc & 1) * STAGE;
        const uint32_t bB = aB + 2 * TILE;
#pragma unroll
        for (int ks = 0; ks < 2; ++ks) {
            uint32_t ah[4][4], al[4][4];
#pragma unroll
            for (int mt = 0; mt < 4; ++mt) {
                const uint32_t ad = aB +
                    ((wm + mt * 16 + (lane & 15)) * 40 + ks * 16 + (lane >> 4) * 8) * 2;
                ldsm4(ah[mt], ad);
                ldsm4(al[mt], ad + TILE);
            }
#pragma unroll
            for (int np = 0; np < 2; ++np) {
                uint32_t bh[4], bl[4];
                const uint32_t ad = bB +
                    ((wn + np * 16 + (lane & 15)) * 40 + ks * 16 + (lane >> 4) * 8) * 2;
                ldsm4(bh, ad);
                if (useBl) ldsm4(bl, ad + TILE);
                // term-major: same-accumulator distance 8
#pragma unroll
                for (int mt = 0; mt < 4; ++mt)
#pragma unroll
                    for (int hf = 0; hf < 2; ++hf)
                        mma16816(acc[mt][np * 2 + hf], ah[mt], bh[hf], bh[hf + 2]);
                if (useBl) {
#pragma unroll
                    for (int mt = 0; mt < 4; ++mt)
#pragma unroll
                        for (int hf = 0; hf < 2; ++hf)
                            mma16816(acc[mt][np * 2 + hf], ah[mt], bl[hf], bl[hf + 2]);
                }
#pragma unroll
                for (int mt = 0; mt < 4; ++mt)
#pragma unroll
                    for (int hf = 0; hf < 2; ++hf)
                        mma16816(acc[mt][np * 2 + hf], al[mt], bh[hf], bh[hf + 2]);
            }
        }
        __syncthreads();
    }

#pragma unroll
    for (int mt = 0; mt < 4; ++mt)
#pragma unroll
        for (int ri = 0; ri < 2; ++ri) {
            const int m = bm + wm + mt * 16 + ri * 8 + (lane >> 2);
#pragma unroll
            for (int nt = 0; nt < 4; ++nt) {
                const int n = bn + wn + nt * 8 + 2 * (lane & 3);
                float v0 = acc[mt][nt][ri * 2 + 0];
                float v1 = acc[mt][nt][ri * 2 + 1];
                if (mode == 0) {
                    *(float2*)(C + (size_t)m * DM + n) = make_float2(v0, v1);
                } else {
                    if (mode == 2) {
                        const int d = n & 63;   // even
                        const float inv = exp2f((float)d * -0.20762050f);
                        float sn, cs;
                        sincosf((float)m * inv, &sn, &cs);
                        const float a = v0, b = v1;
                        v0 = (a * cs - b * sn) * oscale;
                        v1 = (b * cs + a * sn) * oscale;
                    }
                    const int hh = n >> 6;
                    const int d0 = n & 63;
                    const size_t off = ((size_t)hh * SEQ + m) * DK + d0;
                    uint32_t h, l;
                    split2(v0, v1, h, l);
                    *(uint32_t*)(Ch + off) = h;
                    *(uint32_t*)(Cl + off) = l;
                }
            }
        }
}

// ---------------------------------------------------------------------------
// FA2-style flash attention, causal, fp16 mma.
// Br=128 (8 warps x 16 rows), Bc=64, 2 CTAs/SM. Q pre-scaled by 0.125*log2e.
// S 3-term. P via ex2.approx.f16x2 (packed half2 = mma A-frag directly).
// Row-sum l accumulated IN TENSOR CORE via ones-column V tile (d=64..71 pad):
// exact fp32 Σp, no per-iter shfl reduction. Mask hoisted to last 2 iters.
// ---------------------------------------------------------------------------
#define F_K0  0        // 64x144B hi + lo(+9216)
#define F_K1  18432
#define F_V0  36864    // hi only; bytes 128..143 of each row = ones-column pad
#define F_V1  46080
#define F_Q   55296    // 128x144B hi + lo(+18432)
#define F_TOT 92160

__global__ void __launch_bounds__(256, 2)
flash_tc(const __half* __restrict__ qh, const __half* __restrict__ ql,
         const __half* __restrict__ kh, const __half* __restrict__ kl,
         const __half* __restrict__ vh,
         __half* __restrict__ aoh, __half* __restrict__ aol)
{
    extern __shared__ __align__(128) char sma[];
    const uint32_t sbase = s2u(sma);

    const int h    = blockIdx.y;
    const int qb   = gridDim.x - 1 - blockIdx.x;   // heavy tiles first
    const int tid  = threadIdx.x;
    const int lane = tid & 31;
    const int wid  = tid >> 5;
    const int wm   = wid * 16;
    const int g    = lane >> 2;
    const int tq   = lane & 3;

    const size_t hb = (size_t)h * SEQ * DK;
    const int nkb = 2 * qb + 2;     // number of 64-token blocks

    // ---- prologue: Q (group), K0+V0 (group) ----
    {
        const __half* qgh = qh + hb + (size_t)qb * 128 * DK;
        const __half* qgl = ql + hb + (size_t)qb * 128 * DK;
#pragma unroll
        for (int i = 0; i < 4; ++i) {
            const int idx = i * 256 + tid;
            const int r = idx >> 3;
            const int c = idx & 7;
            cp16(sbase + F_Q + r * 144 + c * 16, qgh + r * 64 + c * 8);
            cp16(sbase + F_Q + 18432 + r * 144 + c * 16, qgl + r * 64 + c * 8);
        }
        CP_COMMIT;
        const __half* kgh = kh + hb;
        const __half* kgl = kl + hb;
        const __half* vgh = vh + hb;
#pragma unroll
        for (int i = 0; i < 2; ++i) {
            const int idx = i * 256 + tid;
            const int r = idx >> 3;        // 0..63
            const int c = idx & 7;
            cp16(sbase + F_K0 + r * 144 + c * 16, kgh + r * 64 + c * 8);
            cp16(sbase + F_K0 + 9216 + r * 144 + c * 16, kgl + r * 64 + c * 8);
            cp16(sbase + F_V0 + r * 144 + c * 16, vgh + r * 64 + c * 8);
        }
        CP_COMMIT;
    }
    // ones-column pad for both V buffers: row bytes 128..143 = {1.0h, 0...}
    // (cp.async only ever writes bytes 0..127 of each V row)
    if (tid < 128) {
        const int buf = tid >> 6;
        const int r = tid & 63;
        uint4* p = (uint4*)(sma + (buf ? F_V1 : F_V0) + r * 144 + 128);
        *p = make_uint4(0x00003c00u, 0u, 0u, 0u);
    }
    CP_WAIT1;
    __syncthreads();

    // ---- Q fragments (resident all kernel) ----
    uint32_t qfh[4][4], qfl[4][4];
#pragma unroll
    for (int d16 = 0; d16 < 4; ++d16) {
        const uint32_t ad = sbase + F_Q +
            ((wm + (lane & 15)) * 72 + d16 * 16 + (lane >> 4) * 8) * 2;
        ldsm4(qfh[d16], ad);
        ldsm4(qfl[d16], ad + 18432);
    }

    float oacc[8][4] = {};
    float oaccL[4] = {};            // ones-column accumulator: col0 = sum(p)
    float mrow[2] = { -1e30f, -1e30f };

    auto body = [&](int kb, bool domask) {
        __syncthreads();

        // prefetch K,V (kb+1)
        if (kb + 1 < nkb) {
            const __half* kgh = kh + hb + (size_t)(kb + 1) * 64 * DK;
            const __half* kgl = kl + hb + (size_t)(kb + 1) * 64 * DK;
            const __half* vgh = vh + hb + (size_t)(kb + 1) * 64 * DK;
            const uint32_t kB = sbase + (((kb + 1) & 1) ? F_K1 : F_K0);
            const uint32_t vB = sbase + (((kb + 1) & 1) ? F_V1 : F_V0);
#pragma unroll
            for (int i = 0; i < 2; ++i) {
                const int idx = i * 256 + tid;
                const int r = idx >> 3;
                const int c = idx & 7;
                cp16(kB + r * 144 + c * 16, kgh + r * 64 + c * 8);
                cp16(kB + 9216 + r * 144 + c * 16, kgl + r * 64 + c * 8);
                cp16(vB + r * 144 + c * 16, vgh + r * 64 + c * 8);
            }
        }
        CP_COMMIT;
        CP_WAIT1;
        __syncthreads();

        const uint32_t kBuf = sbase + ((kb & 1) ? F_K1 : F_K0);
        const uint32_t vBuf = sbase + ((kb & 1) ? F_V1 : F_V0);

        // ---- S = Q K^T (3-term, term-major interleave) ----
        float sacc[8][4] = {};
#pragma unroll
        for (int d16 = 0; d16 < 4; ++d16) {
#pragma unroll
            for (int ng = 0; ng < 4; ++ng) {
                uint32_t bh[4], bl[4];
                const uint32_t ad = kBuf +
                    ((ng * 16 + (lane & 15)) * 72 + d16 * 16 + (lane >> 4) * 8) * 2;
                ldsm4(bh, ad);
                ldsm4(bl, ad + 9216);
                mma16816(sacc[2 * ng],     qfh[d16], bh[0], bh[2]);
                mma16816(sacc[2 * ng + 1], qfh[d16], bh[1], bh[3]);
                mma16816(sacc[2 * ng],     qfh[d16], bl[0], bl[2]);
                mma16816(sacc[2 * ng + 1], qfh[d16], bl[1], bl[3]);
                mma16816(sacc[2 * ng],     qfl[d16], bh[0], bh[2]);
                mma16816(sacc[2 * ng + 1], qfl[d16], bh[1], bh[3]);
            }
        }

        // ---- warp-local online softmax (log2 domain), P -> half2 regs ----
        const int moff = (kb - 2 * qb) * 64;    // used only when domask
        uint32_t ph2[8][2];
        float corr[2];
#pragma unroll
        for (int hf = 0; hf < 2; ++hf) {
            const int rloc = wm + g + hf * 8;
            float vmax = -1e30f;
#pragma unroll
            for (int j = 0; j < 8; ++j)
#pragma unroll
                for (int ci = 0; ci < 2; ++ci) {
                    float v = sacc[j][hf * 2 + ci];
                    if (domask && (moff + 8 * j + 2 * tq + ci) > rloc) {
                        v = -1e30f;
                        sacc[j][hf * 2 + ci] = v;
                    }
                    vmax = fmaxf(vmax, v);
                }
            vmax = fmaxf(vmax, __shfl_xor_sync(0xffffffffu, vmax, 1));
            vmax = fmaxf(vmax, __shfl_xor_sync(0xffffffffu, vmax, 2));
            const float mnew = fmaxf(mrow[hf], vmax);
            corr[hf] = exp2f(mrow[hf] - mnew);
            mrow[hf] = mnew;
#pragma unroll
            for (int j = 0; j < 8; ++j)
                ph2[j][hf] = h2exp2(cvt_h2(sacc[j][hf * 2 + 0] - mnew,
                                           sacc[j][hf * 2 + 1] - mnew));
#pragma unroll
            for (int j = 0; j < 8; ++j) {
                oacc[j][hf * 2 + 0] *= corr[hf];
                oacc[j][hf * 2 + 1] *= corr[hf];
            }
            oaccL[hf * 2 + 0] *= corr[hf];
            oaccL[hf * 2 + 1] *= corr[hf];
        }

        // ---- O += P V ; l += P·1 (ones column) ----
#pragma unroll
        for (int kt = 0; kt < 4; ++kt) {
            uint32_t ah[4];
            ah[0] = ph2[2 * kt][0];
            ah[1] = ph2[2 * kt][1];
            ah[2] = ph2[2 * kt + 1][0];
            ah[3] = ph2[2 * kt + 1][1];
            const int t_loc = kt * 16 + (lane & 7) + ((lane >> 3) & 1) * 8;
#pragma unroll
            for (int ng = 0; ng < 4; ++ng) {
                uint32_t bh[4];
                const int d_loc = ng * 16 + ((lane >> 4) & 1) * 8;
                const uint32_t ad = vBuf + (uint32_t)(t_loc * 72 + d_loc) * 2;
                ldsm4t(bh, ad);
                mma16816(oacc[2 * ng],     ah, bh[0], bh[1]);
                mma16816(oacc[2 * ng + 1], ah, bh[2], bh[3]);
            }
            {
                uint32_t bo[2];
                ldsm2t(bo, vBuf + (uint32_t)(t_loc * 72 + 64) * 2);
                mma16816(oaccL, ah, bo[0], bo[1]);
            }
        }
    };

    for (int kb = 0; kb < nkb - 2; ++kb) body(kb, false);
    body(nkb - 2, true);
    body(nkb - 1, true);

    // ---- epilogue: l from ones-column (col 0 -> tq==0), broadcast in quad ----
#pragma unroll
    for (int hf = 0; hf < 2; ++hf) {
        const float lv = __shfl_sync(0xffffffffu, oaccL[hf * 2 + 0], lane & ~3);
        const float inv = 1.f / lv;
        const int q = qb * 128 + wm + g + hf * 8;
#pragma unroll
        for (int j = 0; j < 8; ++j) {
            const float v0 = oacc[j][hf * 2 + 0] * inv;
            const float v1 = oacc[j][hf * 2 + 1] * inv;
            const int col = h * 64 + 8 * j + 2 * tq;
            uint32_t hw, lw;
            split2(v0, v1, hw, lw);
            *(uint32_t*)(aoh + (size_t)q * DM + col) = hw;
            *(uint32_t*)(aol + (size_t)q * DM + col) = lw;
        }
    }
}

// ---------------------------------------------------------------------------
extern "C" void kernel_launch(void* const* d_in, const int* in_sizes, int n_in,
                              void* d_out, int out_size)
{
    const float* x  = (const float*)d_in[0];
    const float* Wq = (const float*)d_in[1];
    const float* Wk = (const float*)d_in[2];
    const float* Wv = (const float*)d_in[3];
    const float* Wo = (const float*)d_in[4];

    __half *xh, *xl, *wh, *wl, *qhp, *qlp, *khp, *klp, *vhp, *aoh, *aol;
    cudaGetSymbolAddress((void**)&xh,  g_xh);
    cudaGetSymbolAddress((void**)&xl,  g_xl);
    cudaGetSymbolAddress((void**)&wh,  g_wh);
    cudaGetSymbolAddress((void**)&wl,  g_wl);
    cudaGetSymbolAddress((void**)&qhp, g_qh);
    cudaGetSymbolAddress((void**)&qlp, g_ql);
    cudaGetSymbolAddress((void**)&khp, g_kh);
    cudaGetSymbolAddress((void**)&klp, g_kl);
    cudaGetSymbolAddress((void**)&vhp, g_vh);
    cudaGetSymbolAddress((void**)&aoh, g_aoh);
    cudaGetSymbolAddress((void**)&aol, g_aol);

    const int nx2 = SEQ * DM / 2;
    const int nw2 = DM * DM / 2;
    split_bf16<<<(nx2 + 255) / 256, 256>>>(x, xh, xl, nx2);
    split4_bf16<<<dim3((nw2 + 255) / 256, 4), 256>>>(Wq, Wk, Wv, Wo, wh, wl, nw2);

    const int gsm = 2 * 4 * 10240;   // 81,920 B
    cudaFuncSetAttribute(gemm_mma, cudaFuncAttributeMaxDynamicSharedMemorySize, gsm);
    cudaFuncSetAttribute(flash_tc, cudaFuncAttributeMaxDynamicSharedMemorySize, F_TOT);

    // fused Q/K/V projections (Q pre-scaled by 0.125*log2e); V lo -> dummy
    // target aol, fully overwritten by flash epilogue afterwards.
    gemm_mma<<<dim3(DM / 128, SEQ / 128, 3), 256, gsm>>>(
        xh, xl, wh, wl, nullptr, qhp, qlp, khp, klp, vhp, aol, 1);

    flash_tc<<<dim3(SEQ / 128, NH), 256, F_TOT>>>(qhp, qlp, khp, klp, vhp, aoh, aol);

    // Wo projection (2-term, weights hi only)
    gemm_mma<<<dim3(DM / 128, SEQ / 128, 1), 256, gsm>>>(
        aoh, aol, wh, wl, (float*)d_out,
        nullptr, nullptr, nullptr, nullptr, nullptr, nullptr, 0);
}